// round 4
// baseline (speedup 1.0000x reference)
#include <cuda_runtime.h>
#include <math.h>

// ---------------------------------------------------------------------------
// EdgeAttention: 4-scale 1x1-conv projections -> nearest-upsample ->
// pairwise per-pixel cosine similarity averaged over locations -> softmax.
//
// Phase 1: per-scale SGEMM  P_s[b][l][o] = sum_c W_s[o][c]*F_s[b][c][l] + bias_s[o]
//          (stored LOCATION-MAJOR so phase 2 reads contiguous 256-float vectors)
// Phase 2: per full-res location, 10 dot products among the 4 projected
//          vectors (with nearest-neighbor source indexing), 6 cosine pair
//          sums accumulated per block into scratch (no atomics).
// Phase 3: deterministic reduction + mean + softmax -> 8x4x4 output.
// ---------------------------------------------------------------------------

#define C256 256

// scratch: projections, location-major per scale
__device__ float g_PT0[8 * 6400 * C256];   // 52.4 MB
__device__ float g_PT1[8 * 1600 * C256];   // 13.1 MB
__device__ float g_PT2[8 *  400 * C256];   //  3.3 MB
__device__ float g_PT3[8 *  100 * C256];   //  0.8 MB
__device__ float g_partials[8 * 50 * 6];

__device__ __forceinline__ float* scale_pt(int s) {
    switch (s) {
        case 0: return g_PT0;
        case 1: return g_PT1;
        case 2: return g_PT2;
        default: return g_PT3;
    }
}

// ---------------------------------------------------------------------------
// Phase 1: SGEMM, BM=BN=128, BK=16, 256 threads, 8x8 microtile (split 64+64
// fragments for conflict-free LDS.128). Output written transposed
// (location-major) with bias added.
// ---------------------------------------------------------------------------
__global__ __launch_bounds__(256, 2)
void gemm_proj(const float* __restrict__ W, const float* __restrict__ F,
               const float* __restrict__ bias, int L, int scale)
{
    __shared__ float As[2][16][128];
    __shared__ float Bs[2][16][128];

    const int tid = threadIdx.x;
    const int b   = blockIdx.z;
    const int m0  = blockIdx.y * 128;
    const int n0  = blockIdx.x * 128;

    const float* Fb = F + (size_t)b * C256 * L;
    float*       Pb = scale_pt(scale) + (size_t)b * L * C256;

    const int ty = tid >> 4;          // 0..15
    const int tx = tid & 15;          // 0..15
    const int aRow = tid >> 1;        // 0..127
    const int aCol = (tid & 1) << 3;  // 0 or 8
    const int bRow = tid >> 4;        // 0..15
    const int bCol = (tid & 15) << 3; // 0..120

    float4 stA0, stA1, stB0, stB1;

    // ---- load tile 0 ----
    {
        const float* wp = W + (m0 + aRow) * C256 + aCol;
        stA0 = *(const float4*)(wp);
        stA1 = *(const float4*)(wp + 4);
        int n = n0 + bCol;
        const float* fp = Fb + (size_t)bRow * L + n;
        stB0 = (n     < L) ? *(const float4*)(fp)     : make_float4(0.f,0.f,0.f,0.f);
        stB1 = (n + 4 < L) ? *(const float4*)(fp + 4) : make_float4(0.f,0.f,0.f,0.f);
    }
    {
        As[0][aCol + 0][aRow] = stA0.x; As[0][aCol + 1][aRow] = stA0.y;
        As[0][aCol + 2][aRow] = stA0.z; As[0][aCol + 3][aRow] = stA0.w;
        As[0][aCol + 4][aRow] = stA1.x; As[0][aCol + 5][aRow] = stA1.y;
        As[0][aCol + 6][aRow] = stA1.z; As[0][aCol + 7][aRow] = stA1.w;
        *(float4*)&Bs[0][bRow][bCol]     = stB0;
        *(float4*)&Bs[0][bRow][bCol + 4] = stB1;
    }
    __syncthreads();

    float acc[8][8];
#pragma unroll
    for (int i = 0; i < 8; ++i)
#pragma unroll
        for (int j = 0; j < 8; ++j) acc[i][j] = 0.f;

    for (int kt = 0; kt < 16; ++kt) {
        const int cur = kt & 1;
        if (kt < 15) {
            const float* wp = W + (m0 + aRow) * C256 + (kt + 1) * 16 + aCol;
            stA0 = *(const float4*)(wp);
            stA1 = *(const float4*)(wp + 4);
            int krow = (kt + 1) * 16 + bRow;
            int n = n0 + bCol;
            const float* fp = Fb + (size_t)krow * L + n;
            stB0 = (n     < L) ? *(const float4*)(fp)     : make_float4(0.f,0.f,0.f,0.f);
            stB1 = (n + 4 < L) ? *(const float4*)(fp + 4) : make_float4(0.f,0.f,0.f,0.f);
        }
#pragma unroll
        for (int kk = 0; kk < 16; ++kk) {
            float4 a0 = *(const float4*)&As[cur][kk][ty * 4];
            float4 a1 = *(const float4*)&As[cur][kk][64 + ty * 4];
            float4 b0 = *(const float4*)&Bs[cur][kk][tx * 4];
            float4 b1 = *(const float4*)&Bs[cur][kk][64 + tx * 4];
            float av[8] = {a0.x, a0.y, a0.z, a0.w, a1.x, a1.y, a1.z, a1.w};
            float bv[8] = {b0.x, b0.y, b0.z, b0.w, b1.x, b1.y, b1.z, b1.w};
#pragma unroll
            for (int i = 0; i < 8; ++i)
#pragma unroll
                for (int j = 0; j < 8; ++j)
                    acc[i][j] += av[i] * bv[j];
        }
        if (kt < 15) {
            const int nxt = cur ^ 1;
            As[nxt][aCol + 0][aRow] = stA0.x; As[nxt][aCol + 1][aRow] = stA0.y;
            As[nxt][aCol + 2][aRow] = stA0.z; As[nxt][aCol + 3][aRow] = stA0.w;
            As[nxt][aCol + 4][aRow] = stA1.x; As[nxt][aCol + 5][aRow] = stA1.y;
            As[nxt][aCol + 6][aRow] = stA1.z; As[nxt][aCol + 7][aRow] = stA1.w;
            *(float4*)&Bs[nxt][bRow][bCol]     = stB0;
            *(float4*)&Bs[nxt][bRow][bCol + 4] = stB1;
        }
        __syncthreads();
    }

    // ---- epilogue: bias + transposed (location-major) store ----
    float bv0[4], bv1[4];
#pragma unroll
    for (int i = 0; i < 4; ++i) {
        bv0[i] = bias[m0 + ty * 4 + i];
        bv1[i] = bias[m0 + 64 + ty * 4 + i];
    }
#pragma unroll
    for (int j = 0; j < 8; ++j) {
        int n = n0 + ((j < 4) ? (tx * 4 + j) : (64 + tx * 4 + (j - 4)));
        if (n < L) {
            float* dst = Pb + (size_t)n * C256 + m0;
            float4 o0 = make_float4(acc[0][j] + bv0[0], acc[1][j] + bv0[1],
                                    acc[2][j] + bv0[2], acc[3][j] + bv0[3]);
            float4 o1 = make_float4(acc[4][j] + bv1[0], acc[5][j] + bv1[1],
                                    acc[6][j] + bv1[2], acc[7][j] + bv1[3]);
            *(float4*)(dst + ty * 4)      = o0;
            *(float4*)(dst + 64 + ty * 4) = o1;
        }
    }
}

// ---------------------------------------------------------------------------
// Phase 2: cosine pair sums. One warp per location iteration; 10 dots
// (4 norms + 6 cross) of 256-dim contiguous vectors; per-block partials.
// ---------------------------------------------------------------------------
__device__ __forceinline__ float dot4(float4 a, float4 b) {
    return a.x * b.x + a.y * b.y + a.z * b.z + a.w * b.w;
}

__global__ __launch_bounds__(256)
void pair_sums()
{
    const int b    = blockIdx.y;
    const int blk  = blockIdx.x;          // 0..49, 128 locations each
    const int warp = threadIdx.x >> 5;    // 0..7
    const int lane = threadIdx.x & 31;

    float acc[6] = {0.f, 0.f, 0.f, 0.f, 0.f, 0.f};

    for (int it = 0; it < 16; ++it) {
        const int l = blk * 128 + warp * 16 + it;
        const int h = l / 80;
        const int w = l - h * 80;
        const float4* x0 = (const float4*)(g_PT0 + ((size_t)(b * 6400 + l)) * C256);
        const float4* x1 = (const float4*)(g_PT1 + ((size_t)(b * 1600 + (h >> 1) * 40 + (w >> 1))) * C256);
        const float4* x2 = (const float4*)(g_PT2 + ((size_t)(b *  400 + (h >> 2) * 20 + (w >> 2))) * C256);
        const float4* x3 = (const float4*)(g_PT3 + ((size_t)(b *  100 + (h >> 3) * 10 + (w >> 3))) * C256);

        float d[10];
#pragma unroll
        for (int k = 0; k < 10; ++k) d[k] = 0.f;

#pragma unroll
        for (int p = 0; p < 2; ++p) {
            float4 v0 = x0[p * 32 + lane];
            float4 v1 = x1[p * 32 + lane];
            float4 v2 = x2[p * 32 + lane];
            float4 v3 = x3[p * 32 + lane];
            d[0] += dot4(v0, v0);
            d[1] += dot4(v0, v1);
            d[2] += dot4(v0, v2);
            d[3] += dot4(v0, v3);
            d[4] += dot4(v1, v1);
            d[5] += dot4(v1, v2);
            d[6] += dot4(v1, v3);
            d[7] += dot4(v2, v2);
            d[8] += dot4(v2, v3);
            d[9] += dot4(v3, v3);
        }
#pragma unroll
        for (int off = 16; off > 0; off >>= 1) {
#pragma unroll
            for (int k = 0; k < 10; ++k)
                d[k] += __shfl_xor_sync(0xFFFFFFFFu, d[k], off);
        }
        if (lane == 0) {
            float nn0 = sqrtf(d[0]);
            float nn1 = sqrtf(d[4]);
            float nn2 = sqrtf(d[7]);
            float nn3 = sqrtf(d[9]);
            acc[0] += d[1] / fmaxf(nn0 * nn1, 1e-8f);
            acc[1] += d[2] / fmaxf(nn0 * nn2, 1e-8f);
            acc[2] += d[3] / fmaxf(nn0 * nn3, 1e-8f);
            acc[3] += d[5] / fmaxf(nn1 * nn2, 1e-8f);
            acc[4] += d[6] / fmaxf(nn1 * nn3, 1e-8f);
            acc[5] += d[8] / fmaxf(nn2 * nn3, 1e-8f);
        }
    }

    __shared__ float sh[8][6];
    if (lane == 0) {
#pragma unroll
        for (int k = 0; k < 6; ++k) sh[warp][k] = acc[k];
    }
    __syncthreads();
    if (threadIdx.x < 6) {
        float s = 0.f;
#pragma unroll
        for (int wq = 0; wq < 8; ++wq) s += sh[wq][threadIdx.x];
        g_partials[((size_t)b * 50 + blk) * 6 + threadIdx.x] = s;
    }
}

// ---------------------------------------------------------------------------
// Phase 3: reduce partials, mean, build symmetric 4x4 (diag == 1), softmax.
// ---------------------------------------------------------------------------
__global__ void finalize(float* __restrict__ out)
{
    const int b = threadIdx.x;
    if (b >= 8) return;
    float s[6] = {0.f, 0.f, 0.f, 0.f, 0.f, 0.f};
    for (int blk = 0; blk < 50; ++blk) {
#pragma unroll
        for (int k = 0; k < 6; ++k)
            s[k] += g_partials[((size_t)b * 50 + blk) * 6 + k];
    }
    const float inv = 1.0f / 6400.0f;
    float a[4][4];
    a[0][0] = a[1][1] = a[2][2] = a[3][3] = 1.0f;
    a[0][1] = a[1][0] = s[0] * inv;
    a[0][2] = a[2][0] = s[1] * inv;
    a[0][3] = a[3][0] = s[2] * inv;
    a[1][2] = a[2][1] = s[3] * inv;
    a[1][3] = a[3][1] = s[4] * inv;
    a[2][3] = a[3][2] = s[5] * inv;

    for (int i = 0; i < 4; ++i) {
        float m = a[i][0];
        for (int j = 1; j < 4; ++j) m = fmaxf(m, a[i][j]);
        float e[4], sum = 0.f;
        for (int j = 0; j < 4; ++j) { e[j] = __expf(a[i][j] - m); sum += e[j]; }
        // use precise expf for accuracy
        sum = 0.f;
        for (int j = 0; j < 4; ++j) { e[j] = expf(a[i][j] - m); sum += e[j]; }
        for (int j = 0; j < 4; ++j) out[b * 16 + i * 4 + j] = e[j] / sum;
    }
}

// ---------------------------------------------------------------------------
extern "C" void kernel_launch(void* const* d_in, const int* in_sizes, int n_in,
                              void* d_out, int out_size)
{
    const float* f[4]  = {nullptr, nullptr, nullptr, nullptr};
    const float* w[4]  = {nullptr, nullptr, nullptr, nullptr};
    const float* bs[4] = {nullptr, nullptr, nullptr, nullptr};
    int wi = 0, bi = 0;
    for (int i = 0; i < n_in; ++i) {
        long sz = in_sizes[i];
        const float* p = (const float*)d_in[i];
        if      (sz == 65536)    { if (wi < 4) w[wi++]  = p; }
        else if (sz == 256)      { if (bi < 4) bs[bi++] = p; }
        else if (sz == 13107200) f[0] = p;   // 8*256*6400
        else if (sz == 3276800)  f[1] = p;   // 8*256*1600
        else if (sz == 819200)   f[2] = p;   // 8*256*400
        else if (sz == 204800)   f[3] = p;   // 8*256*100
    }

    const int Ls[4] = {6400, 1600, 400, 100};
    for (int s = 0; s < 4; ++s) {
        dim3 grid((Ls[s] + 127) / 128, 2, 8);
        gemm_proj<<<grid, 256>>>(w[s], f[s], bs[s], Ls[s], s);
    }
    pair_sums<<<dim3(50, 8), 256>>>();
    finalize<<<1, 32>>>((float*)d_out);
}

// round 6
// speedup vs baseline: 1.8990x; 1.8990x over previous
#include <cuda_runtime.h>
#include <cuda_bf16.h>
#include <cstdint>
#include <math.h>

#define C256 256

// ---------------------------------------------------------------------------
// Scratch (device globals; no allocations allowed)
// ---------------------------------------------------------------------------
__device__ __nv_bfloat16 g_Wh[4][C256 * C256];
__device__ __nv_bfloat16 g_Wl[4][C256 * C256];
__device__ __nv_bfloat16 g_Ft0[8 * 6400 * C256];
__device__ __nv_bfloat16 g_Ft1[8 * 1600 * C256];
__device__ __nv_bfloat16 g_Ft2[8 *  400 * C256];
__device__ __nv_bfloat16 g_Ft3[8 *  100 * C256];
__device__ __nv_bfloat16 g_P0[8 * 6400 * C256];
__device__ __nv_bfloat16 g_P1[8 * 1600 * C256];
__device__ __nv_bfloat16 g_P2[8 *  400 * C256];
__device__ __nv_bfloat16 g_P3[8 *  100 * C256];
__device__ float g_partials[8 * 50 * 6];

__device__ __forceinline__ __nv_bfloat16* ft_pt(int s) {
    switch (s) { case 0: return g_Ft0; case 1: return g_Ft1;
                 case 2: return g_Ft2; default: return g_Ft3; }
}
__device__ __forceinline__ __nv_bfloat16* p_pt(int s) {
    switch (s) { case 0: return g_P0; case 1: return g_P1;
                 case 2: return g_P2; default: return g_P3; }
}

__device__ __forceinline__ uint32_t smem_to_u32(const void* p) {
    uint32_t a;
    asm("{ .reg .u64 t; cvta.to.shared.u64 t, %1; cvt.u32.u64 %0, t; }"
        : "=r"(a) : "l"(p));
    return a;
}

// cp.async 16B with byte-size predicate (0 => zero-fill)
#define CP16(dst, src, sz) \
    asm volatile("cp.async.cg.shared.global [%0], [%1], 16, %2;" \
                 :: "r"(dst), "l"(src), "r"(sz))
#define CP_COMMIT() asm volatile("cp.async.commit_group;" ::: "memory")
#define CP_WAIT1()  asm volatile("cp.async.wait_group 1;" ::: "memory")
#define CP_WAIT0()  asm volatile("cp.async.wait_group 0;" ::: "memory")

__device__ __forceinline__ void ldx4(uint32_t* r, uint32_t addr) {
    asm volatile("ldmatrix.sync.aligned.m8n8.x4.shared.b16 {%0,%1,%2,%3}, [%4];"
                 : "=r"(r[0]), "=r"(r[1]), "=r"(r[2]), "=r"(r[3]) : "r"(addr));
}
__device__ __forceinline__ void mma16816(float* d, const uint32_t* a, const uint32_t* b) {
    asm volatile("mma.sync.aligned.m16n8k16.row.col.f32.bf16.bf16.f32 "
                 "{%0,%1,%2,%3}, {%4,%5,%6,%7}, {%8,%9}, {%0,%1,%2,%3};"
                 : "+f"(d[0]), "+f"(d[1]), "+f"(d[2]), "+f"(d[3])
                 : "r"(a[0]), "r"(a[1]), "r"(a[2]), "r"(a[3]), "r"(b[0]), "r"(b[1]));
}

// ---------------------------------------------------------------------------
// Kernel 0: W -> bf16 hi/lo split
// ---------------------------------------------------------------------------
__global__ void prep_w(const float* __restrict__ w0, const float* __restrict__ w1,
                       const float* __restrict__ w2, const float* __restrict__ w3)
{
    const int s = blockIdx.y;
    const float* w = (s == 0) ? w0 : (s == 1) ? w1 : (s == 2) ? w2 : w3;
    const int idx = blockIdx.x * 256 + threadIdx.x;
    const float v = w[idx];
    const __nv_bfloat16 hi = __float2bfloat16(v);
    g_Wh[s][idx] = hi;
    g_Wl[s][idx] = __float2bfloat16(v - __bfloat162float(hi));
}

// ---------------------------------------------------------------------------
// Kernel 1: F[b][c][l] fp32 -> Ft[b][l][c] bf16 (tiled transpose)
// ---------------------------------------------------------------------------
__global__ void transpose_bf16(const float* __restrict__ F, int scale, int L)
{
    __shared__ float tile[32][33];
    const int b  = blockIdx.z;
    const int l0 = blockIdx.x * 32;
    const int c0 = blockIdx.y * 32;
    const int tx = threadIdx.x, ty = threadIdx.y;
    const float* Fb = F + (size_t)b * C256 * L;
#pragma unroll
    for (int i = 0; i < 4; ++i) {
        const int c = c0 + ty + i * 8;
        const int l = l0 + tx;
        tile[ty + i * 8][tx] = (l < L) ? Fb[(size_t)c * L + l] : 0.f;
    }
    __syncthreads();
    __nv_bfloat16* Ft = ft_pt(scale) + (size_t)b * L * C256;
#pragma unroll
    for (int i = 0; i < 4; ++i) {
        const int l = l0 + ty + i * 8;
        const int c = c0 + tx;
        if (l < L) Ft[(size_t)l * C256 + c] = __float2bfloat16(tile[tx][ty + i * 8]);
    }
}

// ---------------------------------------------------------------------------
// Kernel 2: HMMA bf16 GEMM  P[l][o] = (Wh+Wl)[o][:] . Ft[l][:] + bias[o]
// BM=BN=128, BK=32, 256 threads (2x4 warps, warp tile 64x32), cp.async
// double buffer, pad-8 smem rows (80B) for conflict-free ldmatrix.
// ---------------------------------------------------------------------------
#define ROWB 80u           // 32 bf16 + 8 pad
#define TILEB (128u * ROWB)        // 10240
#define STAGEB (3u * TILEB)        // 30720: [Ahi][Alo][B]
#define GEMM_SMEM (2u * STAGEB)    // 61440

__global__ __launch_bounds__(256)
void gemm_hmma(const float* __restrict__ bias, int scale, int L)
{
    extern __shared__ char sm[];
    const uint32_t sb = smem_to_u32(sm);
    const int tid = threadIdx.x;
    const int wid = tid >> 5, lane = tid & 31;
    const int b = blockIdx.z, m0 = blockIdx.y * 128, l0 = blockIdx.x * 128;

    const __nv_bfloat16* Wh = g_Wh[scale];
    const __nv_bfloat16* Wl = g_Wl[scale];
    const __nv_bfloat16* Ft = ft_pt(scale) + (size_t)b * L * C256;
    __nv_bfloat16*       P  = p_pt(scale)  + (size_t)b * L * C256;

    // ---- per-thread load slots: row = tid>>1 (0..127), two 16B chunks ----
    const int row = tid >> 1;
    const int c2  = (tid & 1) * 2;                 // chunk index 0 or 2
    const uint32_t dOff = row * ROWB + c2 * 16;
    const char* srcAh = (const char*)(Wh + (size_t)(m0 + row) * C256) + c2 * 16;
    const char* srcAl = (const char*)(Wl + (size_t)(m0 + row) * C256) + c2 * 16;
    const int nrow = l0 + row;
    const uint32_t bsz = (nrow < L) ? 16u : 0u;
    const char* srcB = (const char*)(Ft + (size_t)((nrow < L) ? nrow : (L - 1)) * C256) + c2 * 16;

#define ISSUE(kc, s) do {                                                      \
        const uint32_t base = sb + (uint32_t)(s) * STAGEB;                     \
        const int ko = (kc) * 64;                                              \
        CP16(base + dOff,               srcAh + ko,      16u);                 \
        CP16(base + dOff + 16,          srcAh + ko + 16, 16u);                 \
        CP16(base + TILEB + dOff,       srcAl + ko,      16u);                 \
        CP16(base + TILEB + dOff + 16,  srcAl + ko + 16, 16u);                 \
        CP16(base + 2*TILEB + dOff,     srcB + ko,       bsz);                 \
        CP16(base + 2*TILEB + dOff + 16, srcB + ko + 16, bsz);                 \
        CP_COMMIT();                                                          \
    } while (0)

    float acc[4][4][4];
#pragma unroll
    for (int i = 0; i < 4; ++i)
#pragma unroll
        for (int j = 0; j < 4; ++j)
#pragma unroll
            for (int k = 0; k < 4; ++k) acc[i][j][k] = 0.f;

    // ldmatrix address bases (within a stage)
    const int r8 = lane & 7, sel = lane >> 3;
    const int warp_m = wid >> 2, warp_n = wid & 3;
    // A: matrices (m0-7,k0-7),(m8-15,k0-7),(m0-7,k8-15),(m8-15,k8-15)
    const uint32_t aRel = (uint32_t)((warp_m * 64 + r8 + (sel & 1) * 8) * ROWB + (sel >> 1) * 16);
    // B: matrices (n0-7,k0-7),(n0-7,k8-15),(n8-15,k0-7),(n8-15,k8-15)
    const uint32_t bRel = (uint32_t)(2 * TILEB +
                          (warp_n * 32 + r8 + ((sel >> 1) & 1) * 8) * ROWB + (sel & 1) * 16);

    ISSUE(0, 0);
    for (int kc = 0; kc < 8; ++kc) {
        const int s = kc & 1;
        if (kc < 7) { ISSUE(kc + 1, s ^ 1); CP_WAIT1(); }
        else        { CP_WAIT0(); }
        __syncthreads();

        const uint32_t stage = sb + (uint32_t)s * STAGEB;
#pragma unroll
        for (int ks = 0; ks < 2; ++ks) {
            uint32_t bf[8];
            ldx4(bf,     stage + bRel + ks * 32);
            ldx4(bf + 4, stage + bRel + ks * 32 + 16 * ROWB);
            uint32_t af[4];
#pragma unroll
            for (int mt = 0; mt < 4; ++mt) {
                ldx4(af, stage + aRel + ks * 32 + mt * 16 * ROWB);
#pragma unroll
                for (int nt = 0; nt < 4; ++nt)
                    mma16816(acc[mt][nt], af, bf + nt * 2);
            }
#pragma unroll
            for (int mt = 0; mt < 4; ++mt) {
                ldx4(af, stage + TILEB + aRel + ks * 32 + mt * 16 * ROWB);
#pragma unroll
                for (int nt = 0; nt < 4; ++nt)
                    mma16816(acc[mt][nt], af, bf + nt * 2);
            }
        }
        __syncthreads();
    }

    // ---- epilogue: bias add, stage [n][m] bf16 in smem, coalesced store ----
    // smem layout: 128 n-rows x (128 m + 8 pad) bf16, row stride 272B
    {
        float bv[4][2];
#pragma unroll
        for (int mt = 0; mt < 4; ++mt) {
            const int m = warp_m * 64 + mt * 16 + (lane >> 2);
            bv[mt][0] = bias[m0 + m];
            bv[mt][1] = bias[m0 + m + 8];
        }
        __nv_bfloat16* ep = (__nv_bfloat16*)sm;
#pragma unroll
        for (int mt = 0; mt < 4; ++mt) {
            const int m = warp_m * 64 + mt * 16 + (lane >> 2);
#pragma unroll
            for (int nt = 0; nt < 4; ++nt) {
                const int n = warp_n * 32 + nt * 8 + (lane & 3) * 2;
                ep[(size_t)n       * 136 + m]     = __float2bfloat16(acc[mt][nt][0] + bv[mt][0]);
                ep[(size_t)(n + 1) * 136 + m]     = __float2bfloat16(acc[mt][nt][1] + bv[mt][0]);
                ep[(size_t)n       * 136 + m + 8] = __float2bfloat16(acc[mt][nt][2] + bv[mt][1]);
                ep[(size_t)(n + 1) * 136 + m + 8] = __float2bfloat16(acc[mt][nt][3] + bv[mt][1]);
            }
        }
        __syncthreads();
        const int n = tid >> 1, half = tid & 1;
        if (l0 + n < L) {
            const uint4* src = (const uint4*)((const char*)sm + (size_t)n * 272 + half * 128);
            uint4* dst = (uint4*)(P + (size_t)(l0 + n) * C256 + m0 + half * 64);
#pragma unroll
            for (int i = 0; i < 8; ++i) dst[i] = src[i];
        }
    }
#undef ISSUE
}

// ---------------------------------------------------------------------------
// Phase 2: cosine pair sums over bf16 projections (warp per location iter)
// ---------------------------------------------------------------------------
__device__ __forceinline__ void cvt8(uint4 u, float* f) {
    uint32_t v[4] = {u.x, u.y, u.z, u.w};
#pragma unroll
    for (int i = 0; i < 4; ++i) {
        const __nv_bfloat162 h = *reinterpret_cast<__nv_bfloat162*>(&v[i]);
        const float2 p = __bfloat1622float2(h);
        f[2 * i]     = p.x;
        f[2 * i + 1] = p.y;
    }
}

__global__ __launch_bounds__(256)
void pair_sums()
{
    const int b    = blockIdx.y;
    const int blk  = blockIdx.x;          // 0..49, 128 locations each
    const int warp = threadIdx.x >> 5;
    const int lane = threadIdx.x & 31;

    float acc[6] = {0.f, 0.f, 0.f, 0.f, 0.f, 0.f};

    for (int it = 0; it < 16; ++it) {
        const int l = blk * 128 + warp * 16 + it;
        const int h = l / 80;
        const int w = l - h * 80;
        const uint4* x0 = (const uint4*)(g_P0 + (size_t)(b * 6400 + l) * C256);
        const uint4* x1 = (const uint4*)(g_P1 + (size_t)(b * 1600 + (h >> 1) * 40 + (w >> 1)) * C256);
        const uint4* x2 = (const uint4*)(g_P2 + (size_t)(b *  400 + (h >> 2) * 20 + (w >> 2)) * C256);
        const uint4* x3 = (const uint4*)(g_P3 + (size_t)(b *  100 + (h >> 3) * 10 + (w >> 3)) * C256);

        float a0[8], a1[8], a2[8], a3[8];
        cvt8(x0[lane], a0);
        cvt8(x1[lane], a1);
        cvt8(x2[lane], a2);
        cvt8(x3[lane], a3);

        float d[10];
#pragma unroll
        for (int k = 0; k < 10; ++k) d[k] = 0.f;
#pragma unroll
        for (int e = 0; e < 8; ++e) {
            d[0] += a0[e] * a0[e];
            d[1] += a0[e] * a1[e];
            d[2] += a0[e] * a2[e];
            d[3] += a0[e] * a3[e];
            d[4] += a1[e] * a1[e];
            d[5] += a1[e] * a2[e];
            d[6] += a1[e] * a3[e];
            d[7] += a2[e] * a2[e];
            d[8] += a2[e] * a3[e];
            d[9] += a3[e] * a3[e];
        }
#pragma unroll
        for (int off = 16; off > 0; off >>= 1) {
#pragma unroll
            for (int k = 0; k < 10; ++k)
                d[k] += __shfl_xor_sync(0xFFFFFFFFu, d[k], off);
        }
        if (lane == 0) {
            const float nn0 = sqrtf(d[0]);
            const float nn1 = sqrtf(d[4]);
            const float nn2 = sqrtf(d[7]);
            const float nn3 = sqrtf(d[9]);
            acc[0] += d[1] / fmaxf(nn0 * nn1, 1e-8f);
            acc[1] += d[2] / fmaxf(nn0 * nn2, 1e-8f);
            acc[2] += d[3] / fmaxf(nn0 * nn3, 1e-8f);
            acc[3] += d[5] / fmaxf(nn1 * nn2, 1e-8f);
            acc[4] += d[6] / fmaxf(nn1 * nn3, 1e-8f);
            acc[5] += d[8] / fmaxf(nn2 * nn3, 1e-8f);
        }
    }

    __shared__ float sh[8][6];
    if (lane == 0) {
#pragma unroll
        for (int k = 0; k < 6; ++k) sh[warp][k] = acc[k];
    }
    __syncthreads();
    if (threadIdx.x < 6) {
        float s = 0.f;
#pragma unroll
        for (int wq = 0; wq < 8; ++wq) s += sh[wq][threadIdx.x];
        g_partials[((size_t)b * 50 + blk) * 6 + threadIdx.x] = s;
    }
}

// ---------------------------------------------------------------------------
// Phase 3: reduce partials, mean, symmetric 4x4 (diag == 1), softmax.
// ---------------------------------------------------------------------------
__global__ void finalize(float* __restrict__ out)
{
    const int b = threadIdx.x;
    if (b >= 8) return;
    float s[6] = {0.f, 0.f, 0.f, 0.f, 0.f, 0.f};
    for (int blk = 0; blk < 50; ++blk) {
#pragma unroll
        for (int k = 0; k < 6; ++k)
            s[k] += g_partials[((size_t)b * 50 + blk) * 6 + k];
    }
    const float inv = 1.0f / 6400.0f;
    float a[4][4];
    a[0][0] = a[1][1] = a[2][2] = a[3][3] = 1.0f;
    a[0][1] = a[1][0] = s[0] * inv;
    a[0][2] = a[2][0] = s[1] * inv;
    a[0][3] = a[3][0] = s[2] * inv;
    a[1][2] = a[2][1] = s[3] * inv;
    a[1][3] = a[3][1] = s[4] * inv;
    a[2][3] = a[3][2] = s[5] * inv;

    for (int i = 0; i < 4; ++i) {
        float m = a[i][0];
        for (int j = 1; j < 4; ++j) m = fmaxf(m, a[i][j]);
        float e[4], sum = 0.f;
        for (int j = 0; j < 4; ++j) { e[j] = expf(a[i][j] - m); sum += e[j]; }
        for (int j = 0; j < 4; ++j) out[b * 16 + i * 4 + j] = e[j] / sum;
    }
}

// ---------------------------------------------------------------------------
extern "C" void kernel_launch(void* const* d_in, const int* in_sizes, int n_in,
                              void* d_out, int out_size)
{
    const float* f[4]  = {nullptr, nullptr, nullptr, nullptr};
    const float* w[4]  = {nullptr, nullptr, nullptr, nullptr};
    const float* bs[4] = {nullptr, nullptr, nullptr, nullptr};
    int wi = 0, bi = 0;
    for (int i = 0; i < n_in; ++i) {
        long sz = in_sizes[i];
        const float* p = (const float*)d_in[i];
        if      (sz == 65536)    { if (wi < 4) w[wi++]  = p; }
        else if (sz == 256)      { if (bi < 4) bs[bi++] = p; }
        else if (sz == 13107200) f[0] = p;   // 8*256*6400
        else if (sz == 3276800)  f[1] = p;   // 8*256*1600
        else if (sz == 819200)   f[2] = p;   // 8*256*400
        else if (sz == 204800)   f[3] = p;   // 8*256*100
    }

    const int Ls[4] = {6400, 1600, 400, 100};

    prep_w<<<dim3(256, 4), 256>>>(w[0], w[1], w[2], w[3]);

    for (int s = 0; s < 4; ++s) {
        dim3 grid((Ls[s] + 31) / 32, 8, 8);
        transpose_bf16<<<grid, dim3(32, 8)>>>(f[s], s, Ls[s]);
    }

    cudaFuncSetAttribute(gemm_hmma, cudaFuncAttributeMaxDynamicSharedMemorySize, GEMM_SMEM);
    for (int s = 0; s < 4; ++s) {
        dim3 grid((Ls[s] + 127) / 128, 2, 8);
        gemm_hmma<<<grid, 256, GEMM_SMEM>>>(bs[s], s, Ls[s]);
    }

    pair_sums<<<dim3(50, 8), 256>>>();
    finalize<<<1, 32>>>((float*)d_out);
}

// round 7
// speedup vs baseline: 2.7265x; 1.4358x over previous
#include <cuda_runtime.h>
#include <cuda_bf16.h>
#include <cstdint>
#include <math.h>

#define C256 256

// ---------------------------------------------------------------------------
// Scratch (device globals; no allocations allowed)
// ---------------------------------------------------------------------------
__device__ __nv_bfloat16 g_Wh[4][C256 * C256];
__device__ __nv_bfloat16 g_Wl[4][C256 * C256];
__device__ __nv_bfloat16 g_P0[8 * 6400 * C256];
__device__ __nv_bfloat16 g_P1[8 * 1600 * C256];
__device__ __nv_bfloat16 g_P2[8 *  400 * C256];
__device__ __nv_bfloat16 g_P3[8 *  100 * C256];
__device__ float g_partials[8 * 50 * 6];

__device__ __forceinline__ uint32_t smem_to_u32(const void* p) {
    uint32_t a;
    asm("{ .reg .u64 t; cvta.to.shared.u64 t, %1; cvt.u32.u64 %0, t; }"
        : "=r"(a) : "l"(p));
    return a;
}

#define CP16(dst, src, sz) \
    asm volatile("cp.async.cg.shared.global [%0], [%1], 16, %2;" \
                 :: "r"(dst), "l"(src), "r"(sz))
#define CP_COMMIT() asm volatile("cp.async.commit_group;" ::: "memory")
#define CP_WAIT0()  asm volatile("cp.async.wait_group 0;" ::: "memory")

__device__ __forceinline__ void ldx4(uint32_t* r, uint32_t addr) {
    asm volatile("ldmatrix.sync.aligned.m8n8.x4.shared.b16 {%0,%1,%2,%3}, [%4];"
                 : "=r"(r[0]), "=r"(r[1]), "=r"(r[2]), "=r"(r[3]) : "r"(addr));
}
__device__ __forceinline__ void ldx4t(uint32_t* r, uint32_t addr) {
    asm volatile("ldmatrix.sync.aligned.m8n8.x4.trans.shared.b16 {%0,%1,%2,%3}, [%4];"
                 : "=r"(r[0]), "=r"(r[1]), "=r"(r[2]), "=r"(r[3]) : "r"(addr));
}
__device__ __forceinline__ void mma16816(float* d, const uint32_t* a, const uint32_t* b) {
    asm volatile("mma.sync.aligned.m16n8k16.row.col.f32.bf16.bf16.f32 "
                 "{%0,%1,%2,%3}, {%4,%5,%6,%7}, {%8,%9}, {%0,%1,%2,%3};"
                 : "+f"(d[0]), "+f"(d[1]), "+f"(d[2]), "+f"(d[3])
                 : "r"(a[0]), "r"(a[1]), "r"(a[2]), "r"(a[3]), "r"(b[0]), "r"(b[1]));
}

// ---------------------------------------------------------------------------
// Kernel 0: W -> bf16 hi/lo split
// ---------------------------------------------------------------------------
__global__ void prep_w(const float* __restrict__ w0, const float* __restrict__ w1,
                       const float* __restrict__ w2, const float* __restrict__ w3)
{
    const int s = blockIdx.y;
    const float* w = (s == 0) ? w0 : (s == 1) ? w1 : (s == 2) ? w2 : w3;
    const int idx = blockIdx.x * 256 + threadIdx.x;
    const float v = w[idx];
    const __nv_bfloat16 hi = __float2bfloat16(v);
    g_Wh[s][idx] = hi;
    g_Wl[s][idx] = __float2bfloat16(v - __bfloat162float(hi));
}

// ---------------------------------------------------------------------------
// Kernel 1: fused HMMA bf16 GEMM over all 4 scales.
//   P[l][o] = (Wh+Wl)[o][:] . F[:][l] + bias[o]   (F fp32 loaded directly)
// BM=BN=128, BK=32, 256 threads (2x4 warps, warp tile 64x32).
// A (W hi/lo): cp.async double buffer, pad-8 rows (80B stride).
// B (F): LDG fp32 -> reg convert bf16 -> STS [k][n] tile (272B stride),
//        consumed via ldmatrix.x4.trans.
// ---------------------------------------------------------------------------
#define A_ROWB 80u
#define A_TILE (128u * A_ROWB)          // 10240
#define B_ROWB 272u                     // 128 bf16 + 8 pad
#define B_TILE (32u * B_ROWB)           // 8704
#define STAGE  (2u * A_TILE + B_TILE)   // 29184 : [Ahi][Alo][B]
#define GEMM_SMEM (2u * STAGE)          // 58368

__global__ __launch_bounds__(256, 2)
void gemm_fused(const float* __restrict__ f0, const float* __restrict__ f1,
                const float* __restrict__ f2, const float* __restrict__ f3,
                const float* __restrict__ b0, const float* __restrict__ b1,
                const float* __restrict__ b2, const float* __restrict__ b3)
{
    extern __shared__ char sm[];
    const uint32_t sb = smem_to_u32(sm);
    const int tid = threadIdx.x;
    const int wid = tid >> 5, lane = tid & 31;

    // ---- scale lookup (blocks: 800 | 208 | 64 | 16) ----
    const int id = blockIdx.x;
    int s, off, L;
    const float* F;
    const float* bias;
    __nv_bfloat16* P;
    if (id < 800)       { s = 0; off = 0;    L = 6400; F = f0; bias = b0; P = g_P0; }
    else if (id < 1008) { s = 1; off = 800;  L = 1600; F = f1; bias = b1; P = g_P1; }
    else if (id < 1072) { s = 2; off = 1008; L = 400;  F = f2; bias = b2; P = g_P2; }
    else                { s = 3; off = 1072; L = 100;  F = f3; bias = b3; P = g_P3; }
    const int local = id - off;
    const int l0    = (local >> 4) * 128;
    const int rem   = local & 15;
    const int m0    = (rem & 1) * 128;
    const int batch = rem >> 1;

    const __nv_bfloat16* Wh = g_Wh[s];
    const __nv_bfloat16* Wl = g_Wl[s];
    const float* Fb = F + (size_t)batch * C256 * L;
    __nv_bfloat16* Pb = P + (size_t)batch * L * C256;

    // ---- A cp.async slots: row = tid>>1, 32B half selected by tid&1 ----
    const int arow = tid >> 1;
    const int c2   = (tid & 1) * 2;
    const uint32_t aOff = arow * A_ROWB + c2 * 16;
    const char* srcAh = (const char*)(Wh + (size_t)(m0 + arow) * C256) + c2 * 16;
    const char* srcAl = (const char*)(Wl + (size_t)(m0 + arow) * C256) + c2 * 16;

#define ISSUE_A(kc, st) do {                                                  \
        const uint32_t base = sb + (uint32_t)(st) * STAGE;                    \
        const int ko = (kc) * 64;                                             \
        CP16(base + aOff,                   srcAh + ko,      16u);            \
        CP16(base + aOff + 16,              srcAh + ko + 16, 16u);            \
        CP16(base + A_TILE + aOff,          srcAl + ko,      16u);            \
        CP16(base + A_TILE + aOff + 16,     srcAl + ko + 16, 16u);            \
        CP_COMMIT();                                                          \
    } while (0)

    // ---- B load slots: channel = tid>>3, 16 locations at (tid&7)*16 ----
    const int cloc = tid >> 3;            // 0..31
    const int lcol = (tid & 7) * 16;      // 0..112
    float4 v[4];

#define LDG_B(kc) do {                                                        \
        const int ch = (kc) * 32 + cloc;                                      \
        const float* rp = Fb + (size_t)ch * L + l0 + lcol;                    \
        _Pragma("unroll")                                                     \
        for (int i = 0; i < 4; ++i)                                           \
            v[i] = (l0 + lcol + i * 4 < L) ? *(const float4*)(rp + i * 4)     \
                                           : make_float4(0.f, 0.f, 0.f, 0.f); \
    } while (0)

#define STS_B(st) do {                                                        \
        char* bp = sm + (size_t)(st) * STAGE + 2 * A_TILE                     \
                   + (size_t)cloc * B_ROWB + lcol * 2;                        \
        uint4 p0, p1;                                                         \
        __nv_bfloat162 t;                                                     \
        t = __float22bfloat162_rn(make_float2(v[0].x, v[0].y)); p0.x = *(uint32_t*)&t; \
        t = __float22bfloat162_rn(make_float2(v[0].z, v[0].w)); p0.y = *(uint32_t*)&t; \
        t = __float22bfloat162_rn(make_float2(v[1].x, v[1].y)); p0.z = *(uint32_t*)&t; \
        t = __float22bfloat162_rn(make_float2(v[1].z, v[1].w)); p0.w = *(uint32_t*)&t; \
        t = __float22bfloat162_rn(make_float2(v[2].x, v[2].y)); p1.x = *(uint32_t*)&t; \
        t = __float22bfloat162_rn(make_float2(v[2].z, v[2].w)); p1.y = *(uint32_t*)&t; \
        t = __float22bfloat162_rn(make_float2(v[3].x, v[3].y)); p1.z = *(uint32_t*)&t; \
        t = __float22bfloat162_rn(make_float2(v[3].z, v[3].w)); p1.w = *(uint32_t*)&t; \
        *(uint4*)(bp)      = p0;                                              \
        *(uint4*)(bp + 16) = p1;                                              \
    } while (0)

    float acc[4][4][4];
#pragma unroll
    for (int i = 0; i < 4; ++i)
#pragma unroll
        for (int j = 0; j < 4; ++j)
#pragma unroll
            for (int k = 0; k < 4; ++k) acc[i][j][k] = 0.f;

    // ldmatrix relative addresses
    const int r8 = lane & 7, sel = lane >> 3;
    const int warp_m = wid >> 2, warp_n = wid & 3;
    // A (non-trans): matrices (m0-7,k0-7),(m8-15,k0-7),(m0-7,k8-15),(m8-15,k8-15)
    const uint32_t aRel = (uint32_t)((warp_m * 64 + r8 + (sel & 1) * 8) * A_ROWB
                                     + (sel >> 1) * 16);
    // B (trans, [k][n] tile): matrices (k0-7,n0-7),(k8-15,n0-7),(k0-7,n8-15),(k8-15,n8-15)
    const uint32_t bRel = (uint32_t)(2 * A_TILE
                          + ((sel & 1) * 8 + r8) * B_ROWB
                          + (warp_n * 32 + (sel >> 1) * 8) * 2);

    // ---- prologue ----
    LDG_B(0);
    STS_B(0);
    ISSUE_A(0, 0);
    CP_WAIT0();
    __syncthreads();

    for (int kc = 0; kc < 8; ++kc) {
        const int st = kc & 1;
        if (kc < 7) {
            LDG_B(kc + 1);
            ISSUE_A(kc + 1, st ^ 1);
        }

        const uint32_t stage = sb + (uint32_t)st * STAGE;
#pragma unroll
        for (int ks = 0; ks < 2; ++ks) {
            uint32_t bf[8];
            ldx4t(bf,     stage + bRel + ks * 16 * B_ROWB);
            ldx4t(bf + 4, stage + bRel + ks * 16 * B_ROWB + 32);  // n += 16
            uint32_t af[4];
#pragma unroll
            for (int mt = 0; mt < 4; ++mt) {
                ldx4(af, stage + aRel + ks * 32 + mt * 16 * A_ROWB);
#pragma unroll
                for (int nt = 0; nt < 4; ++nt)
                    mma16816(acc[mt][nt], af, bf + (nt >> 1) * 4 + (nt & 1) * 2);
            }
#pragma unroll
            for (int mt = 0; mt < 4; ++mt) {
                ldx4(af, stage + A_TILE + aRel + ks * 32 + mt * 16 * A_ROWB);
#pragma unroll
                for (int nt = 0; nt < 4; ++nt)
                    mma16816(acc[mt][nt], af, bf + (nt >> 1) * 4 + (nt & 1) * 2);
            }
        }

        if (kc < 7) {
            STS_B(st ^ 1);
            CP_WAIT0();
        }
        __syncthreads();
    }

    // ---- epilogue: bias add, stage [n][m] bf16 in smem, coalesced store ----
    {
        float bv[4][2];
#pragma unroll
        for (int mt = 0; mt < 4; ++mt) {
            const int m = warp_m * 64 + mt * 16 + (lane >> 2);
            bv[mt][0] = bias[m0 + m];
            bv[mt][1] = bias[m0 + m + 8];
        }
        __nv_bfloat16* ep = (__nv_bfloat16*)sm;
#pragma unroll
        for (int mt = 0; mt < 4; ++mt) {
            const int m = warp_m * 64 + mt * 16 + (lane >> 2);
#pragma unroll
            for (int nt = 0; nt < 4; ++nt) {
                const int n = warp_n * 32 + nt * 8 + (lane & 3) * 2;
                ep[(size_t)n       * 136 + m]     = __float2bfloat16(acc[mt][nt][0] + bv[mt][0]);
                ep[(size_t)(n + 1) * 136 + m]     = __float2bfloat16(acc[mt][nt][1] + bv[mt][0]);
                ep[(size_t)n       * 136 + m + 8] = __float2bfloat16(acc[mt][nt][2] + bv[mt][1]);
                ep[(size_t)(n + 1) * 136 + m + 8] = __float2bfloat16(acc[mt][nt][3] + bv[mt][1]);
            }
        }
        __syncthreads();
        const int n = tid >> 1, half = tid & 1;
        if (l0 + n < L) {
            const uint4* src = (const uint4*)((const char*)sm + (size_t)n * 272 + half * 128);
            uint4* dst = (uint4*)(Pb + (size_t)(l0 + n) * C256 + m0 + half * 64);
#pragma unroll
            for (int i = 0; i < 8; ++i) dst[i] = src[i];
        }
    }
#undef ISSUE_A
#undef LDG_B
#undef STS_B
}

// ---------------------------------------------------------------------------
// Phase 2: cosine pair sums over bf16 projections (warp per location iter)
// ---------------------------------------------------------------------------
__device__ __forceinline__ void cvt8(uint4 u, float* f) {
    uint32_t v[4] = {u.x, u.y, u.z, u.w};
#pragma unroll
    for (int i = 0; i < 4; ++i) {
        const __nv_bfloat162 h = *reinterpret_cast<__nv_bfloat162*>(&v[i]);
        const float2 p = __bfloat1622float2(h);
        f[2 * i]     = p.x;
        f[2 * i + 1] = p.y;
    }
}

__global__ __launch_bounds__(256)
void pair_sums()
{
    const int b    = blockIdx.y;
    const int blk  = blockIdx.x;          // 0..49, 128 locations each
    const int warp = threadIdx.x >> 5;
    const int lane = threadIdx.x & 31;

    float acc[6] = {0.f, 0.f, 0.f, 0.f, 0.f, 0.f};

    for (int it = 0; it < 16; ++it) {
        const int l = blk * 128 + warp * 16 + it;
        const int h = l / 80;
        const int w = l - h * 80;
        const uint4* x0 = (const uint4*)(g_P0 + (size_t)(b * 6400 + l) * C256);
        const uint4* x1 = (const uint4*)(g_P1 + (size_t)(b * 1600 + (h >> 1) * 40 + (w >> 1)) * C256);
        const uint4* x2 = (const uint4*)(g_P2 + (size_t)(b *  400 + (h >> 2) * 20 + (w >> 2)) * C256);
        const uint4* x3 = (const uint4*)(g_P3 + (size_t)(b *  100 + (h >> 3) * 10 + (w >> 3)) * C256);

        float a0[8], a1[8], a2[8], a3[8];
        cvt8(x0[lane], a0);
        cvt8(x1[lane], a1);
        cvt8(x2[lane], a2);
        cvt8(x3[lane], a3);

        float d[10];
#pragma unroll
        for (int k = 0; k < 10; ++k) d[k] = 0.f;
#pragma unroll
        for (int e = 0; e < 8; ++e) {
            d[0] += a0[e] * a0[e];
            d[1] += a0[e] * a1[e];
            d[2] += a0[e] * a2[e];
            d[3] += a0[e] * a3[e];
            d[4] += a1[e] * a1[e];
            d[5] += a1[e] * a2[e];
            d[6] += a1[e] * a3[e];
            d[7] += a2[e] * a2[e];
            d[8] += a2[e] * a3[e];
            d[9] += a3[e] * a3[e];
        }
#pragma unroll
        for (int off = 16; off > 0; off >>= 1) {
#pragma unroll
            for (int k = 0; k < 10; ++k)
                d[k] += __shfl_xor_sync(0xFFFFFFFFu, d[k], off);
        }
        if (lane == 0) {
            const float nn0 = sqrtf(d[0]);
            const float nn1 = sqrtf(d[4]);
            const float nn2 = sqrtf(d[7]);
            const float nn3 = sqrtf(d[9]);
            acc[0] += d[1] / fmaxf(nn0 * nn1, 1e-8f);
            acc[1] += d[2] / fmaxf(nn0 * nn2, 1e-8f);
            acc[2] += d[3] / fmaxf(nn0 * nn3, 1e-8f);
            acc[3] += d[5] / fmaxf(nn1 * nn2, 1e-8f);
            acc[4] += d[6] / fmaxf(nn1 * nn3, 1e-8f);
            acc[5] += d[8] / fmaxf(nn2 * nn3, 1e-8f);
        }
    }

    __shared__ float sh[8][6];
    if (lane == 0) {
#pragma unroll
        for (int k = 0; k < 6; ++k) sh[warp][k] = acc[k];
    }
    __syncthreads();
    if (threadIdx.x < 6) {
        float s = 0.f;
#pragma unroll
        for (int wq = 0; wq < 8; ++wq) s += sh[wq][threadIdx.x];
        g_partials[((size_t)b * 50 + blk) * 6 + threadIdx.x] = s;
    }
}

// ---------------------------------------------------------------------------
// Phase 3: reduce partials, mean, symmetric 4x4 (diag == 1), softmax.
// ---------------------------------------------------------------------------
__global__ void finalize(float* __restrict__ out)
{
    const int b = threadIdx.x;
    if (b >= 8) return;
    float s[6] = {0.f, 0.f, 0.f, 0.f, 0.f, 0.f};
    for (int blk = 0; blk < 50; ++blk) {
#pragma unroll
        for (int k = 0; k < 6; ++k)
            s[k] += g_partials[((size_t)b * 50 + blk) * 6 + k];
    }
    const float inv = 1.0f / 6400.0f;
    float a[4][4];
    a[0][0] = a[1][1] = a[2][2] = a[3][3] = 1.0f;
    a[0][1] = a[1][0] = s[0] * inv;
    a[0][2] = a[2][0] = s[1] * inv;
    a[0][3] = a[3][0] = s[2] * inv;
    a[1][2] = a[2][1] = s[3] * inv;
    a[1][3] = a[3][1] = s[4] * inv;
    a[2][3] = a[3][2] = s[5] * inv;

    for (int i = 0; i < 4; ++i) {
        float m = a[i][0];
        for (int j = 1; j < 4; ++j) m = fmaxf(m, a[i][j]);
        float e[4], sum = 0.f;
        for (int j = 0; j < 4; ++j) { e[j] = expf(a[i][j] - m); sum += e[j]; }
        for (int j = 0; j < 4; ++j) out[b * 16 + i * 4 + j] = e[j] / sum;
    }
}

// ---------------------------------------------------------------------------
extern "C" void kernel_launch(void* const* d_in, const int* in_sizes, int n_in,
                              void* d_out, int out_size)
{
    const float* f[4]  = {nullptr, nullptr, nullptr, nullptr};
    const float* w[4]  = {nullptr, nullptr, nullptr, nullptr};
    const float* bs[4] = {nullptr, nullptr, nullptr, nullptr};
    int wi = 0, bi = 0;
    for (int i = 0; i < n_in; ++i) {
        long sz = in_sizes[i];
        const float* p = (const float*)d_in[i];
        if      (sz == 65536)    { if (wi < 4) w[wi++]  = p; }
        else if (sz == 256)      { if (bi < 4) bs[bi++] = p; }
        else if (sz == 13107200) f[0] = p;   // 8*256*6400
        else if (sz == 3276800)  f[1] = p;   // 8*256*1600
        else if (sz == 819200)   f[2] = p;   // 8*256*400
        else if (sz == 204800)   f[3] = p;   // 8*256*100
    }

    prep_w<<<dim3(256, 4), 256>>>(w[0], w[1], w[2], w[3]);

    cudaFuncSetAttribute(gemm_fused, cudaFuncAttributeMaxDynamicSharedMemorySize, GEMM_SMEM);
    gemm_fused<<<1088, 256, GEMM_SMEM>>>(f[0], f[1], f[2], f[3],
                                         bs[0], bs[1], bs[2], bs[3]);

    pair_sums<<<dim3(50, 8), 256>>>();
    finalize<<<1, 32>>>((float*)d_out);
}

// round 8
// speedup vs baseline: 3.1312x; 1.1484x over previous
#include <cuda_runtime.h>
#include <cuda_bf16.h>
#include <cstdint>
#include <math.h>

#define C256 256

// ---------------------------------------------------------------------------
// Scratch (device globals; no allocations allowed)
// ---------------------------------------------------------------------------
__device__ __nv_bfloat16 g_Wh[4][C256 * C256];
__device__ __nv_bfloat16 g_Wl[4][C256 * C256];
__device__ __nv_bfloat16 g_P0[8 * 6400 * C256];
__device__ __nv_bfloat16 g_P1[8 * 1600 * C256];
__device__ __nv_bfloat16 g_P2[8 *  400 * C256];
__device__ __nv_bfloat16 g_P3[8 *  100 * C256];
__device__ float g_partials[8 * 50 * 6];

__device__ __forceinline__ uint32_t smem_to_u32(const void* p) {
    uint32_t a;
    asm("{ .reg .u64 t; cvta.to.shared.u64 t, %1; cvt.u32.u64 %0, t; }"
        : "=r"(a) : "l"(p));
    return a;
}

#define CP16(dst, src, sz) \
    asm volatile("cp.async.cg.shared.global [%0], [%1], 16, %2;" \
                 :: "r"(dst), "l"(src), "r"(sz))
#define CP_COMMIT() asm volatile("cp.async.commit_group;" ::: "memory")
#define CP_WAIT0()  asm volatile("cp.async.wait_group 0;" ::: "memory")

__device__ __forceinline__ void ldx4(uint32_t* r, uint32_t addr) {
    asm volatile("ldmatrix.sync.aligned.m8n8.x4.shared.b16 {%0,%1,%2,%3}, [%4];"
                 : "=r"(r[0]), "=r"(r[1]), "=r"(r[2]), "=r"(r[3]) : "r"(addr));
}
__device__ __forceinline__ void ldx4t(uint32_t* r, uint32_t addr) {
    asm volatile("ldmatrix.sync.aligned.m8n8.x4.trans.shared.b16 {%0,%1,%2,%3}, [%4];"
                 : "=r"(r[0]), "=r"(r[1]), "=r"(r[2]), "=r"(r[3]) : "r"(addr));
}
__device__ __forceinline__ void mma16816(float* d, const uint32_t* a, const uint32_t* b) {
    asm volatile("mma.sync.aligned.m16n8k16.row.col.f32.bf16.bf16.f32 "
                 "{%0,%1,%2,%3}, {%4,%5,%6,%7}, {%8,%9}, {%0,%1,%2,%3};"
                 : "+f"(d[0]), "+f"(d[1]), "+f"(d[2]), "+f"(d[3])
                 : "r"(a[0]), "r"(a[1]), "r"(a[2]), "r"(a[3]), "r"(b[0]), "r"(b[1]));
}

// ---------------------------------------------------------------------------
// Kernel 0: W -> bf16 hi/lo split
// ---------------------------------------------------------------------------
__global__ void prep_w(const float* __restrict__ w0, const float* __restrict__ w1,
                       const float* __restrict__ w2, const float* __restrict__ w3)
{
    const int s = blockIdx.y;
    const float* w = (s == 0) ? w0 : (s == 1) ? w1 : (s == 2) ? w2 : w3;
    const int idx = blockIdx.x * 256 + threadIdx.x;
    const float v = w[idx];
    const __nv_bfloat16 hi = __float2bfloat16(v);
    g_Wh[s][idx] = hi;
    g_Wl[s][idx] = __float2bfloat16(v - __bfloat162float(hi));
}

// ---------------------------------------------------------------------------
// Kernel 1: fused HMMA bf16 GEMM over all 4 scales (unchanged from R7).
// ---------------------------------------------------------------------------
#define A_ROWB 80u
#define A_TILE (128u * A_ROWB)
#define B_ROWB 272u
#define B_TILE (32u * B_ROWB)
#define STAGE  (2u * A_TILE + B_TILE)
#define GEMM_SMEM (2u * STAGE)

__global__ __launch_bounds__(256, 2)
void gemm_fused(const float* __restrict__ f0, const float* __restrict__ f1,
                const float* __restrict__ f2, const float* __restrict__ f3,
                const float* __restrict__ b0, const float* __restrict__ b1,
                const float* __restrict__ b2, const float* __restrict__ b3)
{
    extern __shared__ char sm[];
    const uint32_t sb = smem_to_u32(sm);
    const int tid = threadIdx.x;
    const int wid = tid >> 5, lane = tid & 31;

    const int id = blockIdx.x;
    int s, off, L;
    const float* F;
    const float* bias;
    __nv_bfloat16* P;
    if (id < 800)       { s = 0; off = 0;    L = 6400; F = f0; bias = b0; P = g_P0; }
    else if (id < 1008) { s = 1; off = 800;  L = 1600; F = f1; bias = b1; P = g_P1; }
    else if (id < 1072) { s = 2; off = 1008; L = 400;  F = f2; bias = b2; P = g_P2; }
    else                { s = 3; off = 1072; L = 100;  F = f3; bias = b3; P = g_P3; }
    const int local = id - off;
    const int l0    = (local >> 4) * 128;
    const int rem   = local & 15;
    const int m0    = (rem & 1) * 128;
    const int batch = rem >> 1;

    const __nv_bfloat16* Wh = g_Wh[s];
    const __nv_bfloat16* Wl = g_Wl[s];
    const float* Fb = F + (size_t)batch * C256 * L;
    __nv_bfloat16* Pb = P + (size_t)batch * L * C256;

    const int arow = tid >> 1;
    const int c2   = (tid & 1) * 2;
    const uint32_t aOff = arow * A_ROWB + c2 * 16;
    const char* srcAh = (const char*)(Wh + (size_t)(m0 + arow) * C256) + c2 * 16;
    const char* srcAl = (const char*)(Wl + (size_t)(m0 + arow) * C256) + c2 * 16;

#define ISSUE_A(kc, st) do {                                                  \
        const uint32_t base = sb + (uint32_t)(st) * STAGE;                    \
        const int ko = (kc) * 64;                                             \
        CP16(base + aOff,                   srcAh + ko,      16u);            \
        CP16(base + aOff + 16,              srcAh + ko + 16, 16u);            \
        CP16(base + A_TILE + aOff,          srcAl + ko,      16u);            \
        CP16(base + A_TILE + aOff + 16,     srcAl + ko + 16, 16u);            \
        CP_COMMIT();                                                          \
    } while (0)

    const int cloc = tid >> 3;
    const int lcol = (tid & 7) * 16;
    float4 v[4];

#define LDG_B(kc) do {                                                        \
        const int ch = (kc) * 32 + cloc;                                      \
        const float* rp = Fb + (size_t)ch * L + l0 + lcol;                    \
        _Pragma("unroll")                                                     \
        for (int i = 0; i < 4; ++i)                                           \
            v[i] = (l0 + lcol + i * 4 < L) ? *(const float4*)(rp + i * 4)     \
                                           : make_float4(0.f, 0.f, 0.f, 0.f); \
    } while (0)

#define STS_B(st) do {                                                        \
        char* bp = sm + (size_t)(st) * STAGE + 2 * A_TILE                     \
                   + (size_t)cloc * B_ROWB + lcol * 2;                        \
        uint4 p0, p1;                                                         \
        __nv_bfloat162 t;                                                     \
        t = __float22bfloat162_rn(make_float2(v[0].x, v[0].y)); p0.x = *(uint32_t*)&t; \
        t = __float22bfloat162_rn(make_float2(v[0].z, v[0].w)); p0.y = *(uint32_t*)&t; \
        t = __float22bfloat162_rn(make_float2(v[1].x, v[1].y)); p0.z = *(uint32_t*)&t; \
        t = __float22bfloat162_rn(make_float2(v[1].z, v[1].w)); p0.w = *(uint32_t*)&t; \
        t = __float22bfloat162_rn(make_float2(v[2].x, v[2].y)); p1.x = *(uint32_t*)&t; \
        t = __float22bfloat162_rn(make_float2(v[2].z, v[2].w)); p1.y = *(uint32_t*)&t; \
        t = __float22bfloat162_rn(make_float2(v[3].x, v[3].y)); p1.z = *(uint32_t*)&t; \
        t = __float22bfloat162_rn(make_float2(v[3].z, v[3].w)); p1.w = *(uint32_t*)&t; \
        *(uint4*)(bp)      = p0;                                              \
        *(uint4*)(bp + 16) = p1;                                              \
    } while (0)

    float acc[4][4][4];
#pragma unroll
    for (int i = 0; i < 4; ++i)
#pragma unroll
        for (int j = 0; j < 4; ++j)
#pragma unroll
            for (int k = 0; k < 4; ++k) acc[i][j][k] = 0.f;

    const int r8 = lane & 7, sel = lane >> 3;
    const int warp_m = wid >> 2, warp_n = wid & 3;
    const uint32_t aRel = (uint32_t)((warp_m * 64 + r8 + (sel & 1) * 8) * A_ROWB
                                     + (sel >> 1) * 16);
    const uint32_t bRel = (uint32_t)(2 * A_TILE
                          + ((sel & 1) * 8 + r8) * B_ROWB
                          + (warp_n * 32 + (sel >> 1) * 8) * 2);

    LDG_B(0);
    STS_B(0);
    ISSUE_A(0, 0);
    CP_WAIT0();
    __syncthreads();

    for (int kc = 0; kc < 8; ++kc) {
        const int st = kc & 1;
        if (kc < 7) {
            LDG_B(kc + 1);
            ISSUE_A(kc + 1, st ^ 1);
        }

        const uint32_t stage = sb + (uint32_t)st * STAGE;
#pragma unroll
        for (int ks = 0; ks < 2; ++ks) {
            uint32_t bf[8];
            ldx4t(bf,     stage + bRel + ks * 16 * B_ROWB);
            ldx4t(bf + 4, stage + bRel + ks * 16 * B_ROWB + 32);
            uint32_t af[4];
#pragma unroll
            for (int mt = 0; mt < 4; ++mt) {
                ldx4(af, stage + aRel + ks * 32 + mt * 16 * A_ROWB);
#pragma unroll
                for (int nt = 0; nt < 4; ++nt)
                    mma16816(acc[mt][nt], af, bf + (nt >> 1) * 4 + (nt & 1) * 2);
            }
#pragma unroll
            for (int mt = 0; mt < 4; ++mt) {
                ldx4(af, stage + A_TILE + aRel + ks * 32 + mt * 16 * A_ROWB);
#pragma unroll
                for (int nt = 0; nt < 4; ++nt)
                    mma16816(acc[mt][nt], af, bf + (nt >> 1) * 4 + (nt & 1) * 2);
            }
        }

        if (kc < 7) {
            STS_B(st ^ 1);
            CP_WAIT0();
        }
        __syncthreads();
    }

    {
        float bv[4][2];
#pragma unroll
        for (int mt = 0; mt < 4; ++mt) {
            const int m = warp_m * 64 + mt * 16 + (lane >> 2);
            bv[mt][0] = bias[m0 + m];
            bv[mt][1] = bias[m0 + m + 8];
        }
        __nv_bfloat16* ep = (__nv_bfloat16*)sm;
#pragma unroll
        for (int mt = 0; mt < 4; ++mt) {
            const int m = warp_m * 64 + mt * 16 + (lane >> 2);
#pragma unroll
            for (int nt = 0; nt < 4; ++nt) {
                const int n = warp_n * 32 + nt * 8 + (lane & 3) * 2;
                ep[(size_t)n       * 136 + m]     = __float2bfloat16(acc[mt][nt][0] + bv[mt][0]);
                ep[(size_t)(n + 1) * 136 + m]     = __float2bfloat16(acc[mt][nt][1] + bv[mt][0]);
                ep[(size_t)n       * 136 + m + 8] = __float2bfloat16(acc[mt][nt][2] + bv[mt][1]);
                ep[(size_t)(n + 1) * 136 + m + 8] = __float2bfloat16(acc[mt][nt][3] + bv[mt][1]);
            }
        }
        __syncthreads();
        const int n = tid >> 1, half = tid & 1;
        if (l0 + n < L) {
            const uint4* src = (const uint4*)((const char*)sm + (size_t)n * 272 + half * 128);
            uint4* dst = (uint4*)(Pb + (size_t)(l0 + n) * C256 + m0 + half * 64);
#pragma unroll
            for (int i = 0; i < 8; ++i) dst[i] = src[i];
        }
    }
#undef ISSUE_A
#undef LDG_B
#undef STS_B
}

// ---------------------------------------------------------------------------
// Phase 2: cosine pair sums. 8 lanes per pixel (32 ch/lane), 3-round
// butterfly per pixel instead of 5. One warp = 4 pixels per iteration.
// ---------------------------------------------------------------------------
__device__ __forceinline__ void cvt8(uint4 u, float* f) {
    uint32_t v[4] = {u.x, u.y, u.z, u.w};
#pragma unroll
    for (int i = 0; i < 4; ++i) {
        const __nv_bfloat162 h = *reinterpret_cast<__nv_bfloat162*>(&v[i]);
        const float2 p = __bfloat1622float2(h);
        f[2 * i]     = p.x;
        f[2 * i + 1] = p.y;
    }
}

__global__ __launch_bounds__(256)
void pair_sums()
{
    const int b    = blockIdx.y;
    const int blk  = blockIdx.x;          // 0..49, 128 locations each
    const int warp = threadIdx.x >> 5;    // 0..7
    const int lane = threadIdx.x & 31;
    const int g    = lane >> 3;           // pixel group 0..3
    const int q    = lane & 7;            // lane within group

    float acc[6] = {0.f, 0.f, 0.f, 0.f, 0.f, 0.f};

#pragma unroll
    for (int it = 0; it < 4; ++it) {
        const int l = blk * 128 + warp * 16 + it * 4 + g;
        const int h = l / 80;
        const int w = l - h * 80;
        const uint4* x0 = (const uint4*)(g_P0 + (size_t)(b * 6400 + l) * C256);
        const uint4* x1 = (const uint4*)(g_P1 + (size_t)(b * 1600 + (h >> 1) * 40 + (w >> 1)) * C256);
        const uint4* x2 = (const uint4*)(g_P2 + (size_t)(b *  400 + (h >> 2) * 20 + (w >> 2)) * C256);
        const uint4* x3 = (const uint4*)(g_P3 + (size_t)(b *  100 + (h >> 3) * 10 + (w >> 3)) * C256);

        float d[10];
#pragma unroll
        for (int k = 0; k < 10; ++k) d[k] = 0.f;

#pragma unroll
        for (int j = 0; j < 4; ++j) {
            const int idx = q + 8 * j;    // 8 consecutive lanes -> 128B contiguous
            float a0[8], a1[8], a2[8], a3[8];
            cvt8(x0[idx], a0);
            cvt8(x1[idx], a1);
            cvt8(x2[idx], a2);
            cvt8(x3[idx], a3);
#pragma unroll
            for (int e = 0; e < 8; ++e) {
                d[0] += a0[e] * a0[e];
                d[1] += a0[e] * a1[e];
                d[2] += a0[e] * a2[e];
                d[3] += a0[e] * a3[e];
                d[4] += a1[e] * a1[e];
                d[5] += a1[e] * a2[e];
                d[6] += a1[e] * a3[e];
                d[7] += a2[e] * a2[e];
                d[8] += a2[e] * a3[e];
                d[9] += a3[e] * a3[e];
            }
        }
        // reduce within the 8-lane group
#pragma unroll
        for (int off = 4; off > 0; off >>= 1) {
#pragma unroll
            for (int k = 0; k < 10; ++k)
                d[k] += __shfl_xor_sync(0xFFFFFFFFu, d[k], off);
        }
        if (q == 0) {
            const float nn0 = sqrtf(d[0]);
            const float nn1 = sqrtf(d[4]);
            const float nn2 = sqrtf(d[7]);
            const float nn3 = sqrtf(d[9]);
            acc[0] += d[1] / fmaxf(nn0 * nn1, 1e-8f);
            acc[1] += d[2] / fmaxf(nn0 * nn2, 1e-8f);
            acc[2] += d[3] / fmaxf(nn0 * nn3, 1e-8f);
            acc[3] += d[5] / fmaxf(nn1 * nn2, 1e-8f);
            acc[4] += d[6] / fmaxf(nn1 * nn3, 1e-8f);
            acc[5] += d[8] / fmaxf(nn2 * nn3, 1e-8f);
        }
    }

    // 32 group-leaders -> deterministic ordered sum
    __shared__ float sh[32][6];
    if (q == 0) {
#pragma unroll
        for (int k = 0; k < 6; ++k) sh[warp * 4 + g][k] = acc[k];
    }
    __syncthreads();
    if (threadIdx.x < 6) {
        float s = 0.f;
#pragma unroll
        for (int i = 0; i < 32; ++i) s += sh[i][threadIdx.x];
        g_partials[((size_t)b * 50 + blk) * 6 + threadIdx.x] = s;
    }
}

// ---------------------------------------------------------------------------
// Phase 3: parallel reduce (8 blocks, 64 threads), mean, softmax.
// ---------------------------------------------------------------------------
__global__ void finalize(float* __restrict__ out)
{
    const int b = blockIdx.x;     // 0..7
    const int t = threadIdx.x;    // 0..63
    __shared__ float sh[64][6];
#pragma unroll
    for (int k = 0; k < 6; ++k)
        sh[t][k] = (t < 50) ? g_partials[((size_t)b * 50 + t) * 6 + k] : 0.f;
    __syncthreads();
#pragma unroll
    for (int off = 32; off > 0; off >>= 1) {
        if (t < off) {
#pragma unroll
            for (int k = 0; k < 6; ++k) sh[t][k] += sh[t + off][k];
        }
        __syncthreads();
    }
    if (t == 0) {
        const float inv = 1.0f / 6400.0f;
        float a[4][4];
        a[0][0] = a[1][1] = a[2][2] = a[3][3] = 1.0f;
        a[0][1] = a[1][0] = sh[0][0] * inv;
        a[0][2] = a[2][0] = sh[0][1] * inv;
        a[0][3] = a[3][0] = sh[0][2] * inv;
        a[1][2] = a[2][1] = sh[0][3] * inv;
        a[1][3] = a[3][1] = sh[0][4] * inv;
        a[2][3] = a[3][2] = sh[0][5] * inv;
        for (int i = 0; i < 4; ++i) {
            float m = a[i][0];
            for (int j = 1; j < 4; ++j) m = fmaxf(m, a[i][j]);
            float e[4], sum = 0.f;
            for (int j = 0; j < 4; ++j) { e[j] = expf(a[i][j] - m); sum += e[j]; }
            for (int j = 0; j < 4; ++j) out[b * 16 + i * 4 + j] = e[j] / sum;
        }
    }
}

// ---------------------------------------------------------------------------
extern "C" void kernel_launch(void* const* d_in, const int* in_sizes, int n_in,
                              void* d_out, int out_size)
{
    const float* f[4]  = {nullptr, nullptr, nullptr, nullptr};
    const float* w[4]  = {nullptr, nullptr, nullptr, nullptr};
    const float* bs[4] = {nullptr, nullptr, nullptr, nullptr};
    int wi = 0, bi = 0;
    for (int i = 0; i < n_in; ++i) {
        long sz = in_sizes[i];
        const float* p = (const float*)d_in[i];
        if      (sz == 65536)    { if (wi < 4) w[wi++]  = p; }
        else if (sz == 256)      { if (bi < 4) bs[bi++] = p; }
        else if (sz == 13107200) f[0] = p;   // 8*256*6400
        else if (sz == 3276800)  f[1] = p;   // 8*256*1600
        else if (sz == 819200)   f[2] = p;   // 8*256*400
        else if (sz == 204800)   f[3] = p;   // 8*256*100
    }

    prep_w<<<dim3(256, 4), 256>>>(w[0], w[1], w[2], w[3]);

    cudaFuncSetAttribute(gemm_fused, cudaFuncAttributeMaxDynamicSharedMemorySize, GEMM_SMEM);
    gemm_fused<<<1088, 256, GEMM_SMEM>>>(f[0], f[1], f[2], f[3],
                                         bs[0], bs[1], bs[2], bs[3]);

    pair_sums<<<dim3(50, 8), 256>>>();
    finalize<<<8, 64>>>((float*)d_out);
}

// round 9
// speedup vs baseline: 3.9166x; 1.2509x over previous
#include <cuda_runtime.h>
#include <cuda_bf16.h>
#include <cstdint>
#include <math.h>

#define C256 256

// ---------------------------------------------------------------------------
// Scratch (device globals; no allocations allowed)
// ---------------------------------------------------------------------------
__device__ __nv_bfloat16 g_Wh[4][C256 * C256];
__device__ __nv_bfloat16 g_P0[8 * 6400 * C256];
__device__ __nv_bfloat16 g_P1[8 * 1600 * C256];
__device__ __nv_bfloat16 g_P2[8 *  400 * C256];
__device__ __nv_bfloat16 g_P3[8 *  100 * C256];
__device__ float g_partials[8 * 50 * 6];
__device__ unsigned int g_ticket;   // zero-init; last pair_sums block resets it

__device__ __forceinline__ uint32_t smem_to_u32(const void* p) {
    uint32_t a;
    asm("{ .reg .u64 t; cvta.to.shared.u64 t, %1; cvt.u32.u64 %0, t; }"
        : "=r"(a) : "l"(p));
    return a;
}

#define CP16(dst, src, sz) \
    asm volatile("cp.async.cg.shared.global [%0], [%1], 16, %2;" \
                 :: "r"(dst), "l"(src), "r"(sz))
#define CP_COMMIT() asm volatile("cp.async.commit_group;" ::: "memory")
#define CP_WAIT0()  asm volatile("cp.async.wait_group 0;" ::: "memory")

__device__ __forceinline__ void ldx4(uint32_t* r, uint32_t addr) {
    asm volatile("ldmatrix.sync.aligned.m8n8.x4.shared.b16 {%0,%1,%2,%3}, [%4];"
                 : "=r"(r[0]), "=r"(r[1]), "=r"(r[2]), "=r"(r[3]) : "r"(addr));
}
__device__ __forceinline__ void ldx4t(uint32_t* r, uint32_t addr) {
    asm volatile("ldmatrix.sync.aligned.m8n8.x4.trans.shared.b16 {%0,%1,%2,%3}, [%4];"
                 : "=r"(r[0]), "=r"(r[1]), "=r"(r[2]), "=r"(r[3]) : "r"(addr));
}
__device__ __forceinline__ void mma16816(float* d, const uint32_t* a, const uint32_t* b) {
    asm volatile("mma.sync.aligned.m16n8k16.row.col.f32.bf16.bf16.f32 "
                 "{%0,%1,%2,%3}, {%4,%5,%6,%7}, {%8,%9}, {%0,%1,%2,%3};"
                 : "+f"(d[0]), "+f"(d[1]), "+f"(d[2]), "+f"(d[3])
                 : "r"(a[0]), "r"(a[1]), "r"(a[2]), "r"(a[3]), "r"(b[0]), "r"(b[1]));
}

// ---------------------------------------------------------------------------
// Kernel 0: W -> bf16
// ---------------------------------------------------------------------------
__global__ void prep_w(const float* __restrict__ w0, const float* __restrict__ w1,
                       const float* __restrict__ w2, const float* __restrict__ w3)
{
    const int s = blockIdx.y;
    const float* w = (s == 0) ? w0 : (s == 1) ? w1 : (s == 2) ? w2 : w3;
    const int idx = blockIdx.x * 256 + threadIdx.x;
    g_Wh[s][idx] = __float2bfloat16(w[idx]);
}

// ---------------------------------------------------------------------------
// Kernel 1: fused HMMA bf16 GEMM over all 4 scales (W-hi only).
// BM=BN=128, BK=32, 256 threads (2x4 warps, warp tile 64x32).
// ---------------------------------------------------------------------------
#define A_ROWB 80u
#define A_TILE (128u * A_ROWB)          // 10240
#define B_ROWB 272u
#define B_TILE (32u * B_ROWB)           // 8704
#define STAGE  (A_TILE + B_TILE)        // 18944
#define GEMM_SMEM (2u * STAGE)          // 37888

__global__ __launch_bounds__(256, 2)
void gemm_fused(const float* __restrict__ f0, const float* __restrict__ f1,
                const float* __restrict__ f2, const float* __restrict__ f3,
                const float* __restrict__ b0, const float* __restrict__ b1,
                const float* __restrict__ b2, const float* __restrict__ b3)
{
    extern __shared__ char sm[];
    const uint32_t sb = smem_to_u32(sm);
    const int tid = threadIdx.x;
    const int wid = tid >> 5, lane = tid & 31;

    const int id = blockIdx.x;
    int s, off, L;
    const float* F;
    const float* bias;
    __nv_bfloat16* P;
    if (id < 800)       { s = 0; off = 0;    L = 6400; F = f0; bias = b0; P = g_P0; }
    else if (id < 1008) { s = 1; off = 800;  L = 1600; F = f1; bias = b1; P = g_P1; }
    else if (id < 1072) { s = 2; off = 1008; L = 400;  F = f2; bias = b2; P = g_P2; }
    else                { s = 3; off = 1072; L = 100;  F = f3; bias = b3; P = g_P3; }
    const int local = id - off;
    const int l0    = (local >> 4) * 128;
    const int rem   = local & 15;
    const int m0    = (rem & 1) * 128;
    const int batch = rem >> 1;

    const __nv_bfloat16* Wh = g_Wh[s];
    const float* Fb = F + (size_t)batch * C256 * L;
    __nv_bfloat16* Pb = P + (size_t)batch * L * C256;

    const int arow = tid >> 1;
    const int c2   = (tid & 1) * 2;
    const uint32_t aOff = arow * A_ROWB + c2 * 16;
    const char* srcAh = (const char*)(Wh + (size_t)(m0 + arow) * C256) + c2 * 16;

#define ISSUE_A(kc, st) do {                                                  \
        const uint32_t base = sb + (uint32_t)(st) * STAGE;                    \
        const int ko = (kc) * 64;                                             \
        CP16(base + aOff,      srcAh + ko,      16u);                         \
        CP16(base + aOff + 16, srcAh + ko + 16, 16u);                         \
        CP_COMMIT();                                                          \
    } while (0)

    const int cloc = tid >> 3;
    const int lcol = (tid & 7) * 16;
    float4 v[4];

#define LDG_B(kc) do {                                                        \
        const int ch = (kc) * 32 + cloc;                                      \
        const float* rp = Fb + (size_t)ch * L + l0 + lcol;                    \
        _Pragma("unroll")                                                     \
        for (int i = 0; i < 4; ++i)                                           \
            v[i] = (l0 + lcol + i * 4 < L) ? *(const float4*)(rp + i * 4)     \
                                           : make_float4(0.f, 0.f, 0.f, 0.f); \
    } while (0)

#define STS_B(st) do {                                                        \
        char* bp = sm + (size_t)(st) * STAGE + A_TILE                         \
                   + (size_t)cloc * B_ROWB + lcol * 2;                        \
        uint4 p0, p1;                                                         \
        __nv_bfloat162 t;                                                     \
        t = __float22bfloat162_rn(make_float2(v[0].x, v[0].y)); p0.x = *(uint32_t*)&t; \
        t = __float22bfloat162_rn(make_float2(v[0].z, v[0].w)); p0.y = *(uint32_t*)&t; \
        t = __float22bfloat162_rn(make_float2(v[1].x, v[1].y)); p0.z = *(uint32_t*)&t; \
        t = __float22bfloat162_rn(make_float2(v[1].z, v[1].w)); p0.w = *(uint32_t*)&t; \
        t = __float22bfloat162_rn(make_float2(v[2].x, v[2].y)); p1.x = *(uint32_t*)&t; \
        t = __float22bfloat162_rn(make_float2(v[2].z, v[2].w)); p1.y = *(uint32_t*)&t; \
        t = __float22bfloat162_rn(make_float2(v[3].x, v[3].y)); p1.z = *(uint32_t*)&t; \
        t = __float22bfloat162_rn(make_float2(v[3].z, v[3].w)); p1.w = *(uint32_t*)&t; \
        *(uint4*)(bp)      = p0;                                              \
        *(uint4*)(bp + 16) = p1;                                              \
    } while (0)

    float acc[4][4][4];
#pragma unroll
    for (int i = 0; i < 4; ++i)
#pragma unroll
        for (int j = 0; j < 4; ++j)
#pragma unroll
            for (int k = 0; k < 4; ++k) acc[i][j][k] = 0.f;

    const int r8 = lane & 7, sel = lane >> 3;
    const int warp_m = wid >> 2, warp_n = wid & 3;
    const uint32_t aRel = (uint32_t)((warp_m * 64 + r8 + (sel & 1) * 8) * A_ROWB
                                     + (sel >> 1) * 16);
    const uint32_t bRel = (uint32_t)(A_TILE
                          + ((sel & 1) * 8 + r8) * B_ROWB
                          + (warp_n * 32 + (sel >> 1) * 8) * 2);

    LDG_B(0);
    STS_B(0);
    ISSUE_A(0, 0);
    CP_WAIT0();
    __syncthreads();

    for (int kc = 0; kc < 8; ++kc) {
        const int st = kc & 1;
        if (kc < 7) {
            LDG_B(kc + 1);
            ISSUE_A(kc + 1, st ^ 1);
        }

        const uint32_t stage = sb + (uint32_t)st * STAGE;
#pragma unroll
        for (int ks = 0; ks < 2; ++ks) {
            uint32_t bf[8];
            ldx4t(bf,     stage + bRel + ks * 16 * B_ROWB);
            ldx4t(bf + 4, stage + bRel + ks * 16 * B_ROWB + 32);
            uint32_t af[4];
#pragma unroll
            for (int mt = 0; mt < 4; ++mt) {
                ldx4(af, stage + aRel + ks * 32 + mt * 16 * A_ROWB);
#pragma unroll
                for (int nt = 0; nt < 4; ++nt)
                    mma16816(acc[mt][nt], af, bf + (nt >> 1) * 4 + (nt & 1) * 2);
            }
        }

        if (kc < 7) {
            STS_B(st ^ 1);
            CP_WAIT0();
        }
        __syncthreads();
    }

    {
        float bv[4][2];
#pragma unroll
        for (int mt = 0; mt < 4; ++mt) {
            const int m = warp_m * 64 + mt * 16 + (lane >> 2);
            bv[mt][0] = bias[m0 + m];
            bv[mt][1] = bias[m0 + m + 8];
        }
        __nv_bfloat16* ep = (__nv_bfloat16*)sm;
#pragma unroll
        for (int mt = 0; mt < 4; ++mt) {
            const int m = warp_m * 64 + mt * 16 + (lane >> 2);
#pragma unroll
            for (int nt = 0; nt < 4; ++nt) {
                const int n = warp_n * 32 + nt * 8 + (lane & 3) * 2;
                ep[(size_t)n       * 136 + m]     = __float2bfloat16(acc[mt][nt][0] + bv[mt][0]);
                ep[(size_t)(n + 1) * 136 + m]     = __float2bfloat16(acc[mt][nt][1] + bv[mt][0]);
                ep[(size_t)n       * 136 + m + 8] = __float2bfloat16(acc[mt][nt][2] + bv[mt][1]);
                ep[(size_t)(n + 1) * 136 + m + 8] = __float2bfloat16(acc[mt][nt][3] + bv[mt][1]);
            }
        }
        __syncthreads();
        const int n = tid >> 1, half = tid & 1;
        if (l0 + n < L) {
            const uint4* src = (const uint4*)((const char*)sm + (size_t)n * 272 + half * 128);
            uint4* dst = (uint4*)(Pb + (size_t)(l0 + n) * C256 + m0 + half * 64);
#pragma unroll
            for (int i = 0; i < 8; ++i) dst[i] = src[i];
        }
    }
#undef ISSUE_A
#undef LDG_B
#undef STS_B
}

// ---------------------------------------------------------------------------
// Phase 2: cosine pair sums (8 lanes/pixel) + fused finalize in last block.
// ---------------------------------------------------------------------------
__device__ __forceinline__ void cvt8(uint4 u, float* f) {
    uint32_t v[4] = {u.x, u.y, u.z, u.w};
#pragma unroll
    for (int i = 0; i < 4; ++i) {
        const __nv_bfloat162 h = *reinterpret_cast<__nv_bfloat162*>(&v[i]);
        const float2 p = __bfloat1622float2(h);
        f[2 * i]     = p.x;
        f[2 * i + 1] = p.y;
    }
}

__global__ __launch_bounds__(256)
void pair_sums(float* __restrict__ out)
{
    const int b    = blockIdx.y;
    const int blk  = blockIdx.x;          // 0..49, 128 locations each
    const int warp = threadIdx.x >> 5;    // 0..7
    const int lane = threadIdx.x & 31;
    const int g    = lane >> 3;           // pixel group 0..3
    const int q    = lane & 7;            // lane within group

    float acc[6] = {0.f, 0.f, 0.f, 0.f, 0.f, 0.f};

#pragma unroll
    for (int it = 0; it < 4; ++it) {
        const int l = blk * 128 + warp * 16 + it * 4 + g;
        const int h = l / 80;
        const int w = l - h * 80;
        const uint4* x0 = (const uint4*)(g_P0 + (size_t)(b * 6400 + l) * C256);
        const uint4* x1 = (const uint4*)(g_P1 + (size_t)(b * 1600 + (h >> 1) * 40 + (w >> 1)) * C256);
        const uint4* x2 = (const uint4*)(g_P2 + (size_t)(b *  400 + (h >> 2) * 20 + (w >> 2)) * C256);
        const uint4* x3 = (const uint4*)(g_P3 + (size_t)(b *  100 + (h >> 3) * 10 + (w >> 3)) * C256);

        float d[10];
#pragma unroll
        for (int k = 0; k < 10; ++k) d[k] = 0.f;

#pragma unroll
        for (int j = 0; j < 4; ++j) {
            const int idx = q + 8 * j;
            float a0[8], a1[8], a2[8], a3[8];
            cvt8(x0[idx], a0);
            cvt8(x1[idx], a1);
            cvt8(x2[idx], a2);
            cvt8(x3[idx], a3);
#pragma unroll
            for (int e = 0; e < 8; ++e) {
                d[0] += a0[e] * a0[e];
                d[1] += a0[e] * a1[e];
                d[2] += a0[e] * a2[e];
                d[3] += a0[e] * a3[e];
                d[4] += a1[e] * a1[e];
                d[5] += a1[e] * a2[e];
                d[6] += a1[e] * a3[e];
                d[7] += a2[e] * a2[e];
                d[8] += a2[e] * a3[e];
                d[9] += a3[e] * a3[e];
            }
        }
#pragma unroll
        for (int off = 4; off > 0; off >>= 1) {
#pragma unroll
            for (int k = 0; k < 10; ++k)
                d[k] += __shfl_xor_sync(0xFFFFFFFFu, d[k], off);
        }
        if (q == 0) {
            const float nn0 = sqrtf(d[0]);
            const float nn1 = sqrtf(d[4]);
            const float nn2 = sqrtf(d[7]);
            const float nn3 = sqrtf(d[9]);
            acc[0] += d[1] / fmaxf(nn0 * nn1, 1e-8f);
            acc[1] += d[2] / fmaxf(nn0 * nn2, 1e-8f);
            acc[2] += d[3] / fmaxf(nn0 * nn3, 1e-8f);
            acc[3] += d[5] / fmaxf(nn1 * nn2, 1e-8f);
            acc[4] += d[6] / fmaxf(nn1 * nn3, 1e-8f);
            acc[5] += d[8] / fmaxf(nn2 * nn3, 1e-8f);
        }
    }

    // 32 group-leaders -> deterministic ordered sum into shared
    __shared__ float sh[32][6];
    __shared__ unsigned int sh_last;
    if (q == 0) {
#pragma unroll
        for (int k = 0; k < 6; ++k) sh[warp * 4 + g][k] = acc[k];
    }
    __syncthreads();

    // thread 0 writes the block's 6 partials, fences, takes a ticket
    if (threadIdx.x == 0) {
        float* dst = &g_partials[((size_t)b * 50 + blk) * 6];
#pragma unroll
        for (int k = 0; k < 6; ++k) {
            float ss = 0.f;
#pragma unroll
            for (int i = 0; i < 32; ++i) ss += sh[i][k];
            dst[k] = ss;
        }
        __threadfence();
        sh_last = (atomicAdd(&g_ticket, 1u) == 399u);
    }
    __syncthreads();

    // last block: deterministic reduce of all partials + softmax (all batches)
    if (sh_last) {
        __threadfence();
        const int t = threadIdx.x;         // use 48 threads: (batch, pair)
        __shared__ float red[8][6];
        if (t < 48) {
            const int bb = t / 6, k = t % 6;
            float ss = 0.f;
            for (int i = 0; i < 50; ++i)
                ss += g_partials[((size_t)bb * 50 + i) * 6 + k];
            red[bb][k] = ss;
        }
        __syncthreads();
        if (t < 8) {
            const float inv = 1.0f / 6400.0f;
            float a[4][4];
            a[0][0] = a[1][1] = a[2][2] = a[3][3] = 1.0f;
            a[0][1] = a[1][0] = red[t][0] * inv;
            a[0][2] = a[2][0] = red[t][1] * inv;
            a[0][3] = a[3][0] = red[t][2] * inv;
            a[1][2] = a[2][1] = red[t][3] * inv;
            a[1][3] = a[3][1] = red[t][4] * inv;
            a[2][3] = a[3][2] = red[t][5] * inv;
            for (int i = 0; i < 4; ++i) {
                float m = a[i][0];
                for (int j = 1; j < 4; ++j) m = fmaxf(m, a[i][j]);
                float e[4], sum = 0.f;
                for (int j = 0; j < 4; ++j) { e[j] = expf(a[i][j] - m); sum += e[j]; }
                for (int j = 0; j < 4; ++j) out[t * 16 + i * 4 + j] = e[j] / sum;
            }
        }
        if (t == 0) g_ticket = 0;   // reset for next graph replay
    }
}

// ---------------------------------------------------------------------------
extern "C" void kernel_launch(void* const* d_in, const int* in_sizes, int n_in,
                              void* d_out, int out_size)
{
    const float* f[4]  = {nullptr, nullptr, nullptr, nullptr};
    const float* w[4]  = {nullptr, nullptr, nullptr, nullptr};
    const float* bs[4] = {nullptr, nullptr, nullptr, nullptr};
    int wi = 0, bi = 0;
    for (int i = 0; i < n_in; ++i) {
        long sz = in_sizes[i];
        const float* p = (const float*)d_in[i];
        if      (sz == 65536)    { if (wi < 4) w[wi++]  = p; }
        else if (sz == 256)      { if (bi < 4) bs[bi++] = p; }
        else if (sz == 13107200) f[0] = p;   // 8*256*6400
        else if (sz == 3276800)  f[1] = p;   // 8*256*1600
        else if (sz == 819200)   f[2] = p;   // 8*256*400
        else if (sz == 204800)   f[3] = p;   // 8*256*100
    }

    prep_w<<<dim3(256, 4), 256>>>(w[0], w[1], w[2], w[3]);

    cudaFuncSetAttribute(gemm_fused, cudaFuncAttributeMaxDynamicSharedMemorySize, GEMM_SMEM);
    gemm_fused<<<1088, 256, GEMM_SMEM>>>(f[0], f[1], f[2], f[3],
                                         bs[0], bs[1], bs[2], bs[3]);

    pair_sums<<<dim3(50, 8), 256>>>((float*)d_out);
}

// round 10
// speedup vs baseline: 4.3229x; 1.1037x over previous
#include <cuda_runtime.h>
#include <cuda_bf16.h>
#include <cstdint>
#include <math.h>

#define C256 256

// ---------------------------------------------------------------------------
// Scratch (device globals; no allocations allowed)
// ---------------------------------------------------------------------------
__device__ __nv_bfloat16 g_Wh[4][C256 * C256];
__device__ __nv_bfloat16 g_P0[8 * 6400 * C256];
__device__ __nv_bfloat16 g_P1[8 * 1600 * C256];
__device__ __nv_bfloat16 g_P2[8 *  400 * C256];
__device__ __nv_bfloat16 g_P3[8 *  100 * C256];
__device__ float g_partials[8 * 50 * 6];
__device__ unsigned int g_ticket;   // zero-init; last pair_sums block resets it

__device__ __forceinline__ uint32_t smem_to_u32(const void* p) {
    uint32_t a;
    asm("{ .reg .u64 t; cvta.to.shared.u64 t, %1; cvt.u32.u64 %0, t; }"
        : "=r"(a) : "l"(p));
    return a;
}

#define CP16(dst, src, sz) \
    asm volatile("cp.async.cg.shared.global [%0], [%1], 16, %2;" \
                 :: "r"(dst), "l"(src), "r"(sz))
#define CP_COMMIT() asm volatile("cp.async.commit_group;" ::: "memory")
#define CP_WAIT0()  asm volatile("cp.async.wait_group 0;" ::: "memory")

__device__ __forceinline__ void ldx4(uint32_t* r, uint32_t addr) {
    asm volatile("ldmatrix.sync.aligned.m8n8.x4.shared.b16 {%0,%1,%2,%3}, [%4];"
                 : "=r"(r[0]), "=r"(r[1]), "=r"(r[2]), "=r"(r[3]) : "r"(addr));
}
__device__ __forceinline__ void ldx4t(uint32_t* r, uint32_t addr) {
    asm volatile("ldmatrix.sync.aligned.m8n8.x4.trans.shared.b16 {%0,%1,%2,%3}, [%4];"
                 : "=r"(r[0]), "=r"(r[1]), "=r"(r[2]), "=r"(r[3]) : "r"(addr));
}
__device__ __forceinline__ void mma16816(float* d, const uint32_t* a, const uint32_t* b) {
    asm volatile("mma.sync.aligned.m16n8k16.row.col.f32.bf16.bf16.f32 "
                 "{%0,%1,%2,%3}, {%4,%5,%6,%7}, {%8,%9}, {%0,%1,%2,%3};"
                 : "+f"(d[0]), "+f"(d[1]), "+f"(d[2]), "+f"(d[3])
                 : "r"(a[0]), "r"(a[1]), "r"(a[2]), "r"(a[3]), "r"(b[0]), "r"(b[1]));
}

// ---------------------------------------------------------------------------
// Kernel 0: W -> bf16 (float4 vectorized)
// ---------------------------------------------------------------------------
__global__ void prep_w(const float* __restrict__ w0, const float* __restrict__ w1,
                       const float* __restrict__ w2, const float* __restrict__ w3)
{
    const int s = blockIdx.y;
    const float* w = (s == 0) ? w0 : (s == 1) ? w1 : (s == 2) ? w2 : w3;
    const int idx = blockIdx.x * 256 + threadIdx.x;       // grid.x=64 -> 16384 float4
    const float4 v = ((const float4*)w)[idx];
    __nv_bfloat162 lo = __float22bfloat162_rn(make_float2(v.x, v.y));
    __nv_bfloat162 hi = __float22bfloat162_rn(make_float2(v.z, v.w));
    uint2 pk;
    pk.x = *(uint32_t*)&lo;
    pk.y = *(uint32_t*)&hi;
    ((uint2*)g_Wh[s])[idx] = pk;
}

// ---------------------------------------------------------------------------
// Kernel 1: fused HMMA bf16 GEMM over all 4 scales (unchanged from R9).
// ---------------------------------------------------------------------------
#define A_ROWB 80u
#define A_TILE (128u * A_ROWB)
#define B_ROWB 272u
#define B_TILE (32u * B_ROWB)
#define STAGE  (A_TILE + B_TILE)
#define GEMM_SMEM (2u * STAGE)

__global__ __launch_bounds__(256, 2)
void gemm_fused(const float* __restrict__ f0, const float* __restrict__ f1,
                const float* __restrict__ f2, const float* __restrict__ f3,
                const float* __restrict__ b0, const float* __restrict__ b1,
                const float* __restrict__ b2, const float* __restrict__ b3)
{
    extern __shared__ char sm[];
    const uint32_t sb = smem_to_u32(sm);
    const int tid = threadIdx.x;
    const int wid = tid >> 5, lane = tid & 31;

    const int id = blockIdx.x;
    int s, off, L;
    const float* F;
    const float* bias;
    __nv_bfloat16* P;
    if (id < 800)       { s = 0; off = 0;    L = 6400; F = f0; bias = b0; P = g_P0; }
    else if (id < 1008) { s = 1; off = 800;  L = 1600; F = f1; bias = b1; P = g_P1; }
    else if (id < 1072) { s = 2; off = 1008; L = 400;  F = f2; bias = b2; P = g_P2; }
    else                { s = 3; off = 1072; L = 100;  F = f3; bias = b3; P = g_P3; }
    const int local = id - off;
    const int l0    = (local >> 4) * 128;
    const int rem   = local & 15;
    const int m0    = (rem & 1) * 128;
    const int batch = rem >> 1;

    const __nv_bfloat16* Wh = g_Wh[s];
    const float* Fb = F + (size_t)batch * C256 * L;
    __nv_bfloat16* Pb = P + (size_t)batch * L * C256;

    const int arow = tid >> 1;
    const int c2   = (tid & 1) * 2;
    const uint32_t aOff = arow * A_ROWB + c2 * 16;
    const char* srcAh = (const char*)(Wh + (size_t)(m0 + arow) * C256) + c2 * 16;

#define ISSUE_A(kc, st) do {                                                  \
        const uint32_t base = sb + (uint32_t)(st) * STAGE;                    \
        const int ko = (kc) * 64;                                             \
        CP16(base + aOff,      srcAh + ko,      16u);                         \
        CP16(base + aOff + 16, srcAh + ko + 16, 16u);                         \
        CP_COMMIT();                                                          \
    } while (0)

    const int cloc = tid >> 3;
    const int lcol = (tid & 7) * 16;
    float4 v[4];

#define LDG_B(kc) do {                                                        \
        const int ch = (kc) * 32 + cloc;                                      \
        const float* rp = Fb + (size_t)ch * L + l0 + lcol;                    \
        _Pragma("unroll")                                                     \
        for (int i = 0; i < 4; ++i)                                           \
            v[i] = (l0 + lcol + i * 4 < L) ? *(const float4*)(rp + i * 4)     \
                                           : make_float4(0.f, 0.f, 0.f, 0.f); \
    } while (0)

#define STS_B(st) do {                                                        \
        char* bp = sm + (size_t)(st) * STAGE + A_TILE                         \
                   + (size_t)cloc * B_ROWB + lcol * 2;                        \
        uint4 p0, p1;                                                         \
        __nv_bfloat162 t;                                                     \
        t = __float22bfloat162_rn(make_float2(v[0].x, v[0].y)); p0.x = *(uint32_t*)&t; \
        t = __float22bfloat162_rn(make_float2(v[0].z, v[0].w)); p0.y = *(uint32_t*)&t; \
        t = __float22bfloat162_rn(make_float2(v[1].x, v[1].y)); p0.z = *(uint32_t*)&t; \
        t = __float22bfloat162_rn(make_float2(v[1].z, v[1].w)); p0.w = *(uint32_t*)&t; \
        t = __float22bfloat162_rn(make_float2(v[2].x, v[2].y)); p1.x = *(uint32_t*)&t; \
        t = __float22bfloat162_rn(make_float2(v[2].z, v[2].w)); p1.y = *(uint32_t*)&t; \
        t = __float22bfloat162_rn(make_float2(v[3].x, v[3].y)); p1.z = *(uint32_t*)&t; \
        t = __float22bfloat162_rn(make_float2(v[3].z, v[3].w)); p1.w = *(uint32_t*)&t; \
        *(uint4*)(bp)      = p0;                                              \
        *(uint4*)(bp + 16) = p1;                                              \
    } while (0)

    float acc[4][4][4];
#pragma unroll
    for (int i = 0; i < 4; ++i)
#pragma unroll
        for (int j = 0; j < 4; ++j)
#pragma unroll
            for (int k = 0; k < 4; ++k) acc[i][j][k] = 0.f;

    const int r8 = lane & 7, sel = lane >> 3;
    const int warp_m = wid >> 2, warp_n = wid & 3;
    const uint32_t aRel = (uint32_t)((warp_m * 64 + r8 + (sel & 1) * 8) * A_ROWB
                                     + (sel >> 1) * 16);
    const uint32_t bRel = (uint32_t)(A_TILE
                          + ((sel & 1) * 8 + r8) * B_ROWB
                          + (warp_n * 32 + (sel >> 1) * 8) * 2);

    LDG_B(0);
    STS_B(0);
    ISSUE_A(0, 0);
    CP_WAIT0();
    __syncthreads();

    for (int kc = 0; kc < 8; ++kc) {
        const int st = kc & 1;
        if (kc < 7) {
            LDG_B(kc + 1);
            ISSUE_A(kc + 1, st ^ 1);
        }

        const uint32_t stage = sb + (uint32_t)st * STAGE;
#pragma unroll
        for (int ks = 0; ks < 2; ++ks) {
            uint32_t bf[8];
            ldx4t(bf,     stage + bRel + ks * 16 * B_ROWB);
            ldx4t(bf + 4, stage + bRel + ks * 16 * B_ROWB + 32);
            uint32_t af[4];
#pragma unroll
            for (int mt = 0; mt < 4; ++mt) {
                ldx4(af, stage + aRel + ks * 32 + mt * 16 * A_ROWB);
#pragma unroll
                for (int nt = 0; nt < 4; ++nt)
                    mma16816(acc[mt][nt], af, bf + (nt >> 1) * 4 + (nt & 1) * 2);
            }
        }

        if (kc < 7) {
            STS_B(st ^ 1);
            CP_WAIT0();
        }
        __syncthreads();
    }

    {
        float bv[4][2];
#pragma unroll
        for (int mt = 0; mt < 4; ++mt) {
            const int m = warp_m * 64 + mt * 16 + (lane >> 2);
            bv[mt][0] = bias[m0 + m];
            bv[mt][1] = bias[m0 + m + 8];
        }
        __nv_bfloat16* ep = (__nv_bfloat16*)sm;
#pragma unroll
        for (int mt = 0; mt < 4; ++mt) {
            const int m = warp_m * 64 + mt * 16 + (lane >> 2);
#pragma unroll
            for (int nt = 0; nt < 4; ++nt) {
                const int n = warp_n * 32 + nt * 8 + (lane & 3) * 2;
                ep[(size_t)n       * 136 + m]     = __float2bfloat16(acc[mt][nt][0] + bv[mt][0]);
                ep[(size_t)(n + 1) * 136 + m]     = __float2bfloat16(acc[mt][nt][1] + bv[mt][0]);
                ep[(size_t)n       * 136 + m + 8] = __float2bfloat16(acc[mt][nt][2] + bv[mt][1]);
                ep[(size_t)(n + 1) * 136 + m + 8] = __float2bfloat16(acc[mt][nt][3] + bv[mt][1]);
            }
        }
        __syncthreads();
        const int n = tid >> 1, half = tid & 1;
        if (l0 + n < L) {
            const uint4* src = (const uint4*)((const char*)sm + (size_t)n * 272 + half * 128);
            uint4* dst = (uint4*)(Pb + (size_t)(l0 + n) * C256 + m0 + half * 64);
#pragma unroll
            for (int i = 0; i < 8; ++i) dst[i] = src[i];
        }
    }
#undef ISSUE_A
#undef LDG_B
#undef STS_B
}

// ---------------------------------------------------------------------------
// Phase 2: cosine pair sums, one 2x2 full-res block per 8-lane group.
// x1/x2/x3 constant over the block: loaded once, coarse pairs counted x4.
// bf16 -> f32 via exact bit expansion (no cvt pipe).
// ---------------------------------------------------------------------------
__device__ __forceinline__ void exp8(uint4 u, float* f) {
    f[0] = __uint_as_float(u.x << 16); f[1] = __uint_as_float(u.x & 0xffff0000u);
    f[2] = __uint_as_float(u.y << 16); f[3] = __uint_as_float(u.y & 0xffff0000u);
    f[4] = __uint_as_float(u.z << 16); f[5] = __uint_as_float(u.z & 0xffff0000u);
    f[6] = __uint_as_float(u.w << 16); f[7] = __uint_as_float(u.w & 0xffff0000u);
}

// accumulator index map:
// 0..3  : D00 for pixels a,b,c,d
// 4..7  : D01 a..d   8..11 : D02 a..d   12..15 : D03 a..d
// 16..21: D11, D22, D33, D12, D13, D23
__global__ __launch_bounds__(256)
void pair_sums(float* __restrict__ out)
{
    const int b    = blockIdx.y;
    const int blk  = blockIdx.x;          // 0..49
    const int warp = threadIdx.x >> 5;    // 0..7
    const int lane = threadIdx.x & 31;
    const int g    = lane >> 3;           // group 0..3
    const int q    = lane & 7;            // lane in group

    const int G  = blk * 32 + warp * 4 + g;   // 2x2 block id, 0..1599
    const int bh = G / 40;
    const int bw = G - bh * 40;
    const int l00 = (2 * bh) * 80 + 2 * bw;

    const uint4* x0a = (const uint4*)(g_P0 + (size_t)(b * 6400 + l00)      * C256);
    const uint4* x0b = (const uint4*)(g_P0 + (size_t)(b * 6400 + l00 + 1)  * C256);
    const uint4* x0c = (const uint4*)(g_P0 + (size_t)(b * 6400 + l00 + 80) * C256);
    const uint4* x0d = (const uint4*)(g_P0 + (size_t)(b * 6400 + l00 + 81) * C256);
    const uint4* x1  = (const uint4*)(g_P1 + (size_t)(b * 1600 + bh * 40 + bw) * C256);
    const uint4* x2  = (const uint4*)(g_P2 + (size_t)(b *  400 + (bh >> 1) * 20 + (bw >> 1)) * C256);
    const uint4* x3  = (const uint4*)(g_P3 + (size_t)(b *  100 + (bh >> 2) * 10 + (bw >> 2)) * C256);

    float d[22];
#pragma unroll
    for (int k = 0; k < 22; ++k) d[k] = 0.f;

#pragma unroll
    for (int j = 0; j < 4; ++j) {
        const int idx = q + 8 * j;
        float fa[8], fb[8], fc[8], fd[8], f1[8], f2[8], f3[8];
        exp8(x0a[idx], fa);
        exp8(x0b[idx], fb);
        exp8(x0c[idx], fc);
        exp8(x0d[idx], fd);
        exp8(x1[idx],  f1);
        exp8(x2[idx],  f2);
        exp8(x3[idx],  f3);
#pragma unroll
        for (int e = 0; e < 8; ++e) {
            d[0]  += fa[e] * fa[e];
            d[1]  += fb[e] * fb[e];
            d[2]  += fc[e] * fc[e];
            d[3]  += fd[e] * fd[e];
            d[4]  += fa[e] * f1[e];
            d[5]  += fb[e] * f1[e];
            d[6]  += fc[e] * f1[e];
            d[7]  += fd[e] * f1[e];
            d[8]  += fa[e] * f2[e];
            d[9]  += fb[e] * f2[e];
            d[10] += fc[e] * f2[e];
            d[11] += fd[e] * f2[e];
            d[12] += fa[e] * f3[e];
            d[13] += fb[e] * f3[e];
            d[14] += fc[e] * f3[e];
            d[15] += fd[e] * f3[e];
            d[16] += f1[e] * f1[e];
            d[17] += f2[e] * f2[e];
            d[18] += f3[e] * f3[e];
            d[19] += f1[e] * f2[e];
            d[20] += f1[e] * f3[e];
            d[21] += f2[e] * f3[e];
        }
    }

    // reduce within the 8-lane group
#pragma unroll
    for (int off = 4; off > 0; off >>= 1) {
#pragma unroll
        for (int k = 0; k < 22; ++k)
            d[k] += __shfl_xor_sync(0xFFFFFFFFu, d[k], off);
    }

    __shared__ float sh[32][6];
    __shared__ unsigned int sh_last;
    if (q == 0) {
        const float n1 = sqrtf(d[16]);
        const float n2 = sqrtf(d[17]);
        const float n3 = sqrtf(d[18]);
        float a01 = 0.f, a02 = 0.f, a03 = 0.f;
#pragma unroll
        for (int p = 0; p < 4; ++p) {
            const float n0 = sqrtf(d[p]);
            a01 += d[4 + p]  / fmaxf(n0 * n1, 1e-8f);
            a02 += d[8 + p]  / fmaxf(n0 * n2, 1e-8f);
            a03 += d[12 + p] / fmaxf(n0 * n3, 1e-8f);
        }
        const int gi = warp * 4 + g;
        sh[gi][0] = a01;
        sh[gi][1] = a02;
        sh[gi][2] = a03;
        sh[gi][3] = 4.f * (d[19] / fmaxf(n1 * n2, 1e-8f));
        sh[gi][4] = 4.f * (d[20] / fmaxf(n1 * n3, 1e-8f));
        sh[gi][5] = 4.f * (d[21] / fmaxf(n2 * n3, 1e-8f));
    }
    __syncthreads();

    if (threadIdx.x == 0) {
        float* dst = &g_partials[((size_t)b * 50 + blk) * 6];
#pragma unroll
        for (int k = 0; k < 6; ++k) {
            float ss = 0.f;
#pragma unroll
            for (int i = 0; i < 32; ++i) ss += sh[i][k];
            dst[k] = ss;
        }
        __threadfence();
        sh_last = (atomicAdd(&g_ticket, 1u) == 399u);
    }
    __syncthreads();

    if (sh_last) {
        __threadfence();
        const int t = threadIdx.x;
        __shared__ float red[8][6];
        if (t < 48) {
            const int bb = t / 6, k = t % 6;
            float ss = 0.f;
            for (int i = 0; i < 50; ++i)
                ss += g_partials[((size_t)bb * 50 + i) * 6 + k];
            red[bb][k] = ss;
        }
        __syncthreads();
        if (t < 8) {
            const float inv = 1.0f / 6400.0f;
            float a[4][4];
            a[0][0] = a[1][1] = a[2][2] = a[3][3] = 1.0f;
            a[0][1] = a[1][0] = red[t][0] * inv;
            a[0][2] = a[2][0] = red[t][1] * inv;
            a[0][3] = a[3][0] = red[t][2] * inv;
            a[1][2] = a[2][1] = red[t][3] * inv;
            a[1][3] = a[3][1] = red[t][4] * inv;
            a[2][3] = a[3][2] = red[t][5] * inv;
            for (int i = 0; i < 4; ++i) {
                float m = a[i][0];
                for (int j = 1; j < 4; ++j) m = fmaxf(m, a[i][j]);
                float e[4], sum = 0.f;
                for (int j = 0; j < 4; ++j) { e[j] = expf(a[i][j] - m); sum += e[j]; }
                for (int j = 0; j < 4; ++j) out[t * 16 + i * 4 + j] = e[j] / sum;
            }
        }
        if (t == 0) g_ticket = 0;
    }
}

// ---------------------------------------------------------------------------
extern "C" void kernel_launch(void* const* d_in, const int* in_sizes, int n_in,
                              void* d_out, int out_size)
{
    const float* f[4]  = {nullptr, nullptr, nullptr, nullptr};
    const float* w[4]  = {nullptr, nullptr, nullptr, nullptr};
    const float* bs[4] = {nullptr, nullptr, nullptr, nullptr};
    int wi = 0, bi = 0;
    for (int i = 0; i < n_in; ++i) {
        long sz = in_sizes[i];
        const float* p = (const float*)d_in[i];
        if      (sz == 65536)    { if (wi < 4) w[wi++]  = p; }
        else if (sz == 256)      { if (bi < 4) bs[bi++] = p; }
        else if (sz == 13107200) f[0] = p;   // 8*256*6400
        else if (sz == 3276800)  f[1] = p;   // 8*256*1600
        else if (sz == 819200)   f[2] = p;   // 8*256*400
        else if (sz == 204800)   f[3] = p;   // 8*256*100
    }

    prep_w<<<dim3(64, 4), 256>>>(w[0], w[1], w[2], w[3]);

    cudaFuncSetAttribute(gemm_fused, cudaFuncAttributeMaxDynamicSharedMemorySize, GEMM_SMEM);
    gemm_fused<<<1088, 256, GEMM_SMEM>>>(f[0], f[1], f[2], f[3],
                                         bs[0], bs[1], bs[2], bs[3]);

    pair_sums<<<dim3(50, 8), 256>>>((float*)d_out);
}